// round 1
// baseline (speedup 1.0000x reference)
#include <cuda_runtime.h>
#include <math.h>

// Problem dims (fixed)
#define MTOT 4096   // B*N
#define ETOT 1024   // embed
#define KDIM 1024
#define SEQ  2048
#define NH   16
#define HDIM 64

// ---------------- scratch (device globals; allocation-free) ----------------
__device__ float g_q[2 * 16 * 2048 * 64];
__device__ float g_k[2 * 16 * 2048 * 64];
__device__ float g_v[2 * 16 * 2048 * 64];
__device__ float g_u[4096 * 1024];
__device__ float g_attn[4096 * 1024];
__device__ float g_gate[4096 * 1024];

// ---------------- tiled SGEMM: C = A @ W^T + bias (+silu) ----------------
// A: [4096,1024] row-major, W: [1024,1024] row-major (torch Linear layout)
// mode 0: plain [M,E] store; mode 1: head-split store [B,H,N,HD]
// act 0: none; act 1: silu
__global__ __launch_bounds__(256) void proj_gemm(
    const float* __restrict__ A, const float* __restrict__ W,
    const float* __restrict__ bias, float* __restrict__ C,
    int mode, int act)
{
    __shared__ float As[16][128];
    __shared__ float Ws[16][128];
    const int tid = threadIdx.x;
    const int tx = tid & 15, ty = tid >> 4;
    const int mBase = blockIdx.y * 128;
    const int nBase = blockIdx.x * 128;

    float acc[8][8];
#pragma unroll
    for (int i = 0; i < 8; i++)
#pragma unroll
        for (int j = 0; j < 8; j++) acc[i][j] = 0.f;

    for (int kb = 0; kb < KDIM; kb += 16) {
#pragma unroll
        for (int t = 0; t < 2; t++) {
            int idx = tid + t * 256;       // 0..511
            int row = idx >> 2;            // 0..127
            int c4  = (idx & 3) << 2;      // 0,4,8,12
            float4 a = *(const float4*)&A[(size_t)(mBase + row) * KDIM + kb + c4];
            As[c4 + 0][row] = a.x; As[c4 + 1][row] = a.y;
            As[c4 + 2][row] = a.z; As[c4 + 3][row] = a.w;
            float4 w = *(const float4*)&W[(size_t)(nBase + row) * KDIM + kb + c4];
            Ws[c4 + 0][row] = w.x; Ws[c4 + 1][row] = w.y;
            Ws[c4 + 2][row] = w.z; Ws[c4 + 3][row] = w.w;
        }
        __syncthreads();
#pragma unroll
        for (int k = 0; k < 16; k++) {
            float a0[8], w0[8];
            *(float4*)&a0[0] = *(const float4*)&As[k][ty * 8];
            *(float4*)&a0[4] = *(const float4*)&As[k][ty * 8 + 4];
            *(float4*)&w0[0] = *(const float4*)&Ws[k][tx * 8];
            *(float4*)&w0[4] = *(const float4*)&Ws[k][tx * 8 + 4];
#pragma unroll
            for (int i = 0; i < 8; i++)
#pragma unroll
                for (int j = 0; j < 8; j++)
                    acc[i][j] = fmaf(a0[i], w0[j], acc[i][j]);
        }
        __syncthreads();
    }

#pragma unroll
    for (int i = 0; i < 8; i++) {
        int m = mBase + ty * 8 + i;
#pragma unroll
        for (int j = 0; j < 8; j++) {
            int e = nBase + tx * 8 + j;
            float v = acc[i][j] + bias[e];
            if (act) v = v / (1.f + __expf(-v));   // silu
            if (mode == 0) {
                C[(size_t)m * ETOT + e] = v;
            } else {
                int b = m >> 11, n = m & (SEQ - 1);
                int h = e >> 6,  d = e & (HDIM - 1);
                C[(((size_t)b * NH + h) * SEQ + n) * HDIM + d] = v;
            }
        }
    }
}

// ---------------- attention: out = relu(q k^T / 8) @ v ----------------
// q,k,v: [B,H,N,HD]; out written merged [M,E] with column offset h*HD.
// Tiles: 128 queries x 64 keys; out accumulator resident (no softmax).
#define QB 128
#define KB 64
#define ATTN_SMEM ((64 * 128 + 64 * 64 + 64 * 64 + 128 * 65) * 4)

__global__ __launch_bounds__(256, 2) void attn_kernel(
    const float* __restrict__ q, const float* __restrict__ k,
    const float* __restrict__ v, float* __restrict__ attn)
{
    extern __shared__ float sm[];
    float* qT = sm;                    // [64][128]  qT[d][i]
    float* kT = qT + 64 * 128;         // [64][64]   kT[d][j]
    float* vS = kT + 64 * 64;          // [64][64]   vS[j][dd]
    float* sS = vS + 64 * 64;          // [128][65]  sS[i][j] (padded pitch)

    const int tid = threadIdx.x;
    const int tx = tid & 15, ty = tid >> 4;
    const int bh = blockIdx.y;                 // 0..31
    const int qBase = blockIdx.x * QB;
    const float* qp = q + (size_t)bh * SEQ * HDIM;
    const float* kp = k + (size_t)bh * SEQ * HDIM;
    const float* vp = v + (size_t)bh * SEQ * HDIM;

    // load q tile transposed: 128 rows x 64 d
#pragma unroll
    for (int t = 0; t < 8; t++) {
        int idx = tid + t * 256;       // 0..2047 (float4 units)
        int row = idx >> 4;            // 0..127
        int c4  = (idx & 15) << 2;     // 0..60
        float4 a = *(const float4*)&qp[(size_t)(qBase + row) * HDIM + c4];
        qT[(c4 + 0) * 128 + row] = a.x; qT[(c4 + 1) * 128 + row] = a.y;
        qT[(c4 + 2) * 128 + row] = a.z; qT[(c4 + 3) * 128 + row] = a.w;
    }

    float out[8][4];
#pragma unroll
    for (int i = 0; i < 8; i++)
#pragma unroll
        for (int j = 0; j < 4; j++) out[i][j] = 0.f;

    for (int kb = 0; kb < SEQ; kb += KB) {
        __syncthreads();  // protect kT/vS/sS from previous iteration readers
        // load k tile transposed + v tile natural: 64x64 each
#pragma unroll
        for (int t = 0; t < 4; t++) {
            int idx = tid + t * 256;   // 0..1023 (float4 units)
            int row = idx >> 4;        // 0..63
            int c4  = (idx & 15) << 2;
            float4 a = *(const float4*)&kp[(size_t)(kb + row) * HDIM + c4];
            kT[(c4 + 0) * 64 + row] = a.x; kT[(c4 + 1) * 64 + row] = a.y;
            kT[(c4 + 2) * 64 + row] = a.z; kT[(c4 + 3) * 64 + row] = a.w;
            float4 b = *(const float4*)&vp[(size_t)(kb + row) * HDIM + c4];
            *(float4*)&vS[row * 64 + c4] = b;
        }
        __syncthreads();

        // phase 2: S[i][j] = sum_d q[i][d] k[j][d]; thread tile 8x4
        float s[8][4];
#pragma unroll
        for (int i = 0; i < 8; i++)
#pragma unroll
            for (int j = 0; j < 4; j++) s[i][j] = 0.f;

#pragma unroll 4
        for (int d = 0; d < 64; d++) {
            float a0[8], b0[4];
            *(float4*)&a0[0] = *(const float4*)&qT[d * 128 + ty * 8];
            *(float4*)&a0[4] = *(const float4*)&qT[d * 128 + ty * 8 + 4];
            *(float4*)&b0[0] = *(const float4*)&kT[d * 64 + tx * 4];
#pragma unroll
            for (int i = 0; i < 8; i++)
#pragma unroll
                for (int j = 0; j < 4; j++)
                    s[i][j] = fmaf(a0[i], b0[j], s[i][j]);
        }
        // scale + relu, stage to smem (padded pitch 65 to avoid conflicts)
#pragma unroll
        for (int i = 0; i < 8; i++)
#pragma unroll
            for (int j = 0; j < 4; j++) {
                float vv = s[i][j] * 0.125f;
                sS[(ty * 8 + i) * 65 + tx * 4 + j] = vv > 0.f ? vv : 0.f;
            }
        __syncthreads();

        // phase 3: out[i][dd] += sum_j S[i][j] v[j][dd]
#pragma unroll 4
        for (int j = 0; j < KB; j++) {
            float b0[4];
            *(float4*)&b0[0] = *(const float4*)&vS[j * 64 + tx * 4];
#pragma unroll
            for (int i = 0; i < 8; i++) {
                float a = sS[(ty * 8 + i) * 65 + j];
                out[i][0] = fmaf(a, b0[0], out[i][0]);
                out[i][1] = fmaf(a, b0[1], out[i][1]);
                out[i][2] = fmaf(a, b0[2], out[i][2]);
                out[i][3] = fmaf(a, b0[3], out[i][3]);
            }
        }
    }

    // store merged: attn[(b*SEQ + n)*ETOT + h*HD + dd]
    const int b = bh >> 4, h = bh & 15;
#pragma unroll
    for (int i = 0; i < 8; i++) {
        size_t rowoff = ((size_t)b * SEQ + qBase + ty * 8 + i) * ETOT + h * HDIM;
#pragma unroll
        for (int j = 0; j < 4; j++)
            attn[rowoff + tx * 4 + j] = out[i][j];
    }
}

// ---------------- layernorm over E + gate by u ----------------
__global__ __launch_bounds__(256) void ln_gate(
    const float* __restrict__ a, const float* __restrict__ u,
    const float* __restrict__ gamma, const float* __restrict__ beta,
    float* __restrict__ o)
{
    const int row = blockIdx.x;
    const int tid = threadIdx.x;
    const float* ar = a + (size_t)row * ETOT;
    float4 xv = *(const float4*)&ar[tid * 4];

    float s1 = xv.x + xv.y + xv.z + xv.w;
    float s2 = xv.x * xv.x + xv.y * xv.y + xv.z * xv.z + xv.w * xv.w;
#pragma unroll
    for (int o2 = 16; o2 > 0; o2 >>= 1) {
        s1 += __shfl_xor_sync(0xffffffffu, s1, o2);
        s2 += __shfl_xor_sync(0xffffffffu, s2, o2);
    }
    __shared__ float r1[8], r2[8];
    __shared__ float mu_s, inv_s;
    if ((tid & 31) == 0) { r1[tid >> 5] = s1; r2[tid >> 5] = s2; }
    __syncthreads();
    if (tid == 0) {
        float t1 = 0.f, t2 = 0.f;
#pragma unroll
        for (int i = 0; i < 8; i++) { t1 += r1[i]; t2 += r2[i]; }
        float mu = t1 * (1.f / ETOT);
        float var = t2 * (1.f / ETOT) - mu * mu;
        mu_s = mu;
        inv_s = rsqrtf(var + 1e-5f);
    }
    __syncthreads();
    const float mu = mu_s, inv = inv_s;

    float4 gv = *(const float4*)&gamma[tid * 4];
    float4 bv = *(const float4*)&beta[tid * 4];
    float4 uv = *(const float4*)&u[(size_t)row * ETOT + tid * 4];
    float4 ov;
    ov.x = ((xv.x - mu) * inv * gv.x + bv.x) * uv.x;
    ov.y = ((xv.y - mu) * inv * gv.y + bv.y) * uv.y;
    ov.z = ((xv.z - mu) * inv * gv.z + bv.z) * uv.z;
    ov.w = ((xv.w - mu) * inv * gv.w + bv.w) * uv.w;
    *(float4*)&o[(size_t)row * ETOT + tid * 4] = ov;
}

// ---------------- launch ----------------
extern "C" void kernel_launch(void* const* d_in, const int* in_sizes, int n_in,
                              void* d_out, int out_size)
{
    const float* x    = (const float*)d_in[0];
    const float* Wq   = (const float*)d_in[1];
    const float* bq   = (const float*)d_in[2];
    const float* Wk   = (const float*)d_in[3];
    const float* bk   = (const float*)d_in[4];
    const float* Wv   = (const float*)d_in[5];
    const float* bv   = (const float*)d_in[6];
    const float* Wu   = (const float*)d_in[7];
    const float* bu   = (const float*)d_in[8];
    const float* Wo   = (const float*)d_in[9];
    const float* bo   = (const float*)d_in[10];
    const float* ln_g = (const float*)d_in[11];
    const float* ln_b = (const float*)d_in[12];

    float *qp, *kp, *vp, *up, *ap, *gp;
    cudaGetSymbolAddress((void**)&qp, g_q);
    cudaGetSymbolAddress((void**)&kp, g_k);
    cudaGetSymbolAddress((void**)&vp, g_v);
    cudaGetSymbolAddress((void**)&up, g_u);
    cudaGetSymbolAddress((void**)&ap, g_attn);
    cudaGetSymbolAddress((void**)&gp, g_gate);

    cudaFuncSetAttribute(attn_kernel,
                         cudaFuncAttributeMaxDynamicSharedMemorySize, ATTN_SMEM);

    dim3 pg(ETOT / 128, MTOT / 128);   // (8, 32)
    proj_gemm<<<pg, 256>>>(x, Wq, bq, qp, 1, 0);
    proj_gemm<<<pg, 256>>>(x, Wk, bk, kp, 1, 0);
    proj_gemm<<<pg, 256>>>(x, Wv, bv, vp, 1, 1);
    proj_gemm<<<pg, 256>>>(x, Wu, bu, up, 0, 1);

    attn_kernel<<<dim3(SEQ / QB, 32), 256, ATTN_SMEM>>>(qp, kp, vp, ap);

    ln_gate<<<MTOT, 256>>>(ap, up, ln_g, ln_b, gp);

    proj_gemm<<<pg, 256>>>(gp, Wo, bo, (float*)d_out, 0, 0);
}

// round 2
// speedup vs baseline: 1.7069x; 1.7069x over previous
#include <cuda_runtime.h>
#include <cuda_bf16.h>
#include <math.h>

// Problem dims (fixed)
#define MTOT 4096   // B*N
#define ETOT 1024
#define KDIM 1024
#define SEQ  2048
#define NH   16
#define HDIM 64

// ---------------- scratch ----------------
__device__ float g_q[2 * 16 * 2048 * 64];
__device__ float g_k[2 * 16 * 2048 * 64];
__device__ float g_v[2 * 16 * 2048 * 64];
__device__ float g_u[4096 * 1024];
__device__ float g_attn[4096 * 1024];
__device__ float g_gate[4096 * 1024];

// ---------------- mma helpers ----------------
__device__ __forceinline__ unsigned smem_u32(const void* p) {
    return (unsigned)__cvta_generic_to_shared(p);
}
__device__ __forceinline__ void ldmat_x4(unsigned addr, unsigned& r0, unsigned& r1,
                                         unsigned& r2, unsigned& r3) {
    asm volatile("ldmatrix.sync.aligned.m8n8.x4.shared.b16 {%0,%1,%2,%3}, [%4];\n"
                 : "=r"(r0), "=r"(r1), "=r"(r2), "=r"(r3) : "r"(addr));
}
__device__ __forceinline__ void ldmat_x4_t(unsigned addr, unsigned& r0, unsigned& r1,
                                           unsigned& r2, unsigned& r3) {
    asm volatile("ldmatrix.sync.aligned.m8n8.x4.trans.shared.b16 {%0,%1,%2,%3}, [%4];\n"
                 : "=r"(r0), "=r"(r1), "=r"(r2), "=r"(r3) : "r"(addr));
}
__device__ __forceinline__ void mma_bf16(float* c, const unsigned* a, const unsigned* b) {
    asm volatile(
        "mma.sync.aligned.m16n8k16.row.col.f32.bf16.bf16.f32 "
        "{%0,%1,%2,%3}, {%4,%5,%6,%7}, {%8,%9}, {%0,%1,%2,%3};\n"
        : "+f"(c[0]), "+f"(c[1]), "+f"(c[2]), "+f"(c[3])
        : "r"(a[0]), "r"(a[1]), "r"(a[2]), "r"(a[3]), "r"(b[0]), "r"(b[1]));
}
__device__ __forceinline__ void split_bf16(float x, __nv_bfloat16& hi, __nv_bfloat16& lo) {
    hi = __float2bfloat16(x);
    lo = __float2bfloat16(x - __bfloat162float(hi));
}

// ================= projection GEMM (3xBF16 tensor-core) =================
// C = A @ W^T + bias (+silu). A [4096,1024], W [1024,1024] (torch Linear).
// CTA tile 128x128, fp32 K-chunk 32 -> bf16 K'=96 (segments A:[hi,lo,hi], W:[hi,hi,lo]).
#define PA 104   // As pitch (bf16 elems), rows 128, cols 96
#define PB 136   // Ws pitch, rows 96 (k'), cols 128
#define PROJ_SMEM ((128 * PA + 96 * PB) * 2)

__global__ __launch_bounds__(256) void proj_mma(
    const float* __restrict__ A, const float* __restrict__ W,
    const float* __restrict__ bias, float* __restrict__ C,
    int mode, int act)
{
    extern __shared__ __nv_bfloat16 smb[];
    __nv_bfloat16* As = smb;             // [128][PA]
    __nv_bfloat16* Ws = smb + 128 * PA;  // [96][PB]

    const int tid = threadIdx.x;
    const int lane = tid & 31, warp = tid >> 5;
    const int warpM = warp >> 1, warpN = warp & 1;
    const int mB = blockIdx.y * 128, nB = blockIdx.x * 128;
    const int g = lane >> 2, tig = lane & 3;

    float acc[2][8][4];
#pragma unroll
    for (int mt = 0; mt < 2; mt++)
#pragma unroll
        for (int nt = 0; nt < 8; nt++)
#pragma unroll
            for (int r = 0; r < 4; r++) acc[mt][nt][r] = 0.f;

    for (int kb = 0; kb < KDIM; kb += 32) {
        __syncthreads();
#pragma unroll
        for (int t = 0; t < 4; t++) {
            int idx = tid + t * 256;          // 0..1023
            int row = idx >> 3;               // 0..127
            int c4  = (idx & 7) << 2;         // 0..28
            float4 a = *(const float4*)&A[(size_t)(mB + row) * KDIM + kb + c4];
            float av[4] = {a.x, a.y, a.z, a.w};
            float4 w = *(const float4*)&W[(size_t)(nB + row) * KDIM + kb + c4];
            float wv[4] = {w.x, w.y, w.z, w.w};
#pragma unroll
            for (int i = 0; i < 4; i++) {
                __nv_bfloat16 hi, lo;
                split_bf16(av[i], hi, lo);
                As[row * PA + c4 + i]      = hi;
                As[row * PA + 32 + c4 + i] = lo;
                As[row * PA + 64 + c4 + i] = hi;
                split_bf16(wv[i], hi, lo);
                Ws[(c4 + i) * PB + row]        = hi;
                Ws[(32 + c4 + i) * PB + row]   = hi;
                Ws[(64 + c4 + i) * PB + row]   = lo;
            }
        }
        __syncthreads();

#pragma unroll
        for (int ks = 0; ks < 6; ks++) {
            const int kk = ks * 16;
            unsigned af[2][4];
#pragma unroll
            for (int mt = 0; mt < 2; mt++) {
                int row = warpM * 32 + mt * 16 + (lane & 15);
                int ko  = kk + ((lane >> 4) << 3);
                ldmat_x4(smem_u32(&As[row * PA + ko]),
                         af[mt][0], af[mt][1], af[mt][2], af[mt][3]);
            }
            unsigned bf[8][2];
#pragma unroll
            for (int nt2 = 0; nt2 < 4; nt2++) {
                int l8 = lane & 7, sel = lane >> 3;
                int kr = kk + ((sel & 1) << 3) + l8;
                int nc = warpN * 64 + nt2 * 16 + ((sel >> 1) << 3);
                unsigned r0, r1, r2, r3;
                ldmat_x4_t(smem_u32(&Ws[kr * PB + nc]), r0, r1, r2, r3);
                bf[nt2 * 2][0] = r0;     bf[nt2 * 2][1] = r1;
                bf[nt2 * 2 + 1][0] = r2; bf[nt2 * 2 + 1][1] = r3;
            }
#pragma unroll
            for (int mt = 0; mt < 2; mt++)
#pragma unroll
                for (int nt = 0; nt < 8; nt++)
                    mma_bf16(acc[mt][nt], af[mt], bf[nt]);
        }
    }

    // epilogue
#pragma unroll
    for (int mt = 0; mt < 2; mt++)
#pragma unroll
        for (int nt = 0; nt < 8; nt++)
#pragma unroll
            for (int r = 0; r < 4; r++) {
                int m = mB + warpM * 32 + mt * 16 + g + ((r >> 1) << 3);
                int e = nB + warpN * 64 + nt * 8 + 2 * tig + (r & 1);
                float v = acc[mt][nt][r] + bias[e];
                if (act) v = v / (1.f + __expf(-v));
                if (mode == 0) {
                    C[(size_t)m * ETOT + e] = v;
                } else {
                    int b = m >> 11, n = m & (SEQ - 1);
                    int h = e >> 6,  d = e & (HDIM - 1);
                    C[(((size_t)b * NH + h) * SEQ + n) * HDIM + d] = v;
                }
            }
}

// ================= attention (3xBF16 tensor-core) =================
// Per (b,h): S = relu(Q K^T / 8), O = S V.  Tiles: 128 q x 64 keys.
// Qs/Ss: [128][K'=192] (A-side, segs [hi,lo,hi]); Ks/Vs: [192][64] (B-side, [hi,hi,lo]).
#define PQ 200
#define PK 72
#define ATTN_SMEM ((128 * PQ + 128 * PQ + 192 * PK + 192 * PK) * 2)

__global__ __launch_bounds__(256) void attn_mma(
    const float* __restrict__ q, const float* __restrict__ k,
    const float* __restrict__ v, float* __restrict__ attn)
{
    extern __shared__ __nv_bfloat16 smb[];
    __nv_bfloat16* Qs = smb;                       // [128][PQ]
    __nv_bfloat16* Ss = Qs + 128 * PQ;             // [128][PQ]
    __nv_bfloat16* Ks = Ss + 128 * PQ;             // [192][PK]
    __nv_bfloat16* Vs = Ks + 192 * PK;             // [192][PK]

    const int tid = threadIdx.x;
    const int lane = tid & 31, warp = tid >> 5;
    const int warpM = warp >> 1, warpN = warp & 1;
    const int bh = blockIdx.y;
    const int qBase = blockIdx.x * 128;
    const int g = lane >> 2, tig = lane & 3;
    const float* qp = q + (size_t)bh * SEQ * HDIM;
    const float* kp = k + (size_t)bh * SEQ * HDIM;
    const float* vp = v + (size_t)bh * SEQ * HDIM;

    // load Q tile once: 128 rows x 64 d
#pragma unroll
    for (int t = 0; t < 8; t++) {
        int idx = tid + t * 256;
        int row = idx >> 4;
        int c4  = (idx & 15) << 2;
        float4 a = *(const float4*)&qp[(size_t)(qBase + row) * HDIM + c4];
        float av[4] = {a.x, a.y, a.z, a.w};
#pragma unroll
        for (int i = 0; i < 4; i++) {
            __nv_bfloat16 hi, lo;
            split_bf16(av[i], hi, lo);
            Qs[row * PQ + c4 + i]       = hi;
            Qs[row * PQ + 64 + c4 + i]  = lo;
            Qs[row * PQ + 128 + c4 + i] = hi;
        }
    }

    float oacc[2][4][4];
#pragma unroll
    for (int mt = 0; mt < 2; mt++)
#pragma unroll
        for (int nt = 0; nt < 4; nt++)
#pragma unroll
            for (int r = 0; r < 4; r++) oacc[mt][nt][r] = 0.f;

    for (int kt = 0; kt < SEQ; kt += 64) {
        __syncthreads();   // Ks/Vs free (also orders first Qs use)
#pragma unroll
        for (int t = 0; t < 4; t++) {
            int idx = tid + t * 256;           // 0..1023
            int row = idx >> 4;                // key j 0..63
            int c4  = (idx & 15) << 2;         // d
            float4 a = *(const float4*)&kp[(size_t)(kt + row) * HDIM + c4];
            float av[4] = {a.x, a.y, a.z, a.w};
            float4 b = *(const float4*)&vp[(size_t)(kt + row) * HDIM + c4];
            float bv[4] = {b.x, b.y, b.z, b.w};
#pragma unroll
            for (int i = 0; i < 4; i++) {
                __nv_bfloat16 hi, lo;
                split_bf16(av[i], hi, lo);          // K transposed: Ks[d'][j]
                Ks[(c4 + i) * PK + row]        = hi;
                Ks[(64 + c4 + i) * PK + row]   = hi;
                Ks[(128 + c4 + i) * PK + row]  = lo;
                split_bf16(bv[i], hi, lo);          // V natural: Vs[j'][d]
                Vs[row * PK + c4 + i]          = hi;
                Vs[(64 + row) * PK + c4 + i]   = hi;
                Vs[(128 + row) * PK + c4 + i]  = lo;
            }
        }
        __syncthreads();

        // ---- phase 2: S = Q K^T ----
        float sacc[2][4][4];
#pragma unroll
        for (int mt = 0; mt < 2; mt++)
#pragma unroll
            for (int nt = 0; nt < 4; nt++)
#pragma unroll
                for (int r = 0; r < 4; r++) sacc[mt][nt][r] = 0.f;

#pragma unroll
        for (int ks = 0; ks < 12; ks++) {
            const int kk = ks * 16;
            unsigned af[2][4];
#pragma unroll
            for (int mt = 0; mt < 2; mt++) {
                int row = warpM * 32 + mt * 16 + (lane & 15);
                int ko  = kk + ((lane >> 4) << 3);
                ldmat_x4(smem_u32(&Qs[row * PQ + ko]),
                         af[mt][0], af[mt][1], af[mt][2], af[mt][3]);
            }
            unsigned bfr[4][2];
#pragma unroll
            for (int nt2 = 0; nt2 < 2; nt2++) {
                int l8 = lane & 7, sel = lane >> 3;
                int kr = kk + ((sel & 1) << 3) + l8;
                int nc = warpN * 32 + nt2 * 16 + ((sel >> 1) << 3);
                unsigned r0, r1, r2, r3;
                ldmat_x4_t(smem_u32(&Ks[kr * PK + nc]), r0, r1, r2, r3);
                bfr[nt2 * 2][0] = r0;     bfr[nt2 * 2][1] = r1;
                bfr[nt2 * 2 + 1][0] = r2; bfr[nt2 * 2 + 1][1] = r3;
            }
#pragma unroll
            for (int mt = 0; mt < 2; mt++)
#pragma unroll
                for (int nt = 0; nt < 4; nt++)
                    mma_bf16(sacc[mt][nt], af[mt], bfr[nt]);
        }

        // scale + relu + split into Ss (A layout [hi,lo,hi] along j)
#pragma unroll
        for (int mt = 0; mt < 2; mt++)
#pragma unroll
            for (int nt = 0; nt < 4; nt++)
#pragma unroll
                for (int r = 0; r < 4; r++) {
                    int row = warpM * 32 + mt * 16 + g + ((r >> 1) << 3);
                    int j   = warpN * 32 + nt * 8 + 2 * tig + (r & 1);
                    float vv = sacc[mt][nt][r] * 0.125f;
                    vv = vv > 0.f ? vv : 0.f;
                    __nv_bfloat16 hi, lo;
                    split_bf16(vv, hi, lo);
                    Ss[row * PQ + j]        = hi;
                    Ss[row * PQ + 64 + j]   = lo;
                    Ss[row * PQ + 128 + j]  = hi;
                }
        __syncthreads();

        // ---- phase 3: O += S V ----
#pragma unroll
        for (int ks = 0; ks < 12; ks++) {
            const int kk = ks * 16;
            unsigned af[2][4];
#pragma unroll
            for (int mt = 0; mt < 2; mt++) {
                int row = warpM * 32 + mt * 16 + (lane & 15);
                int ko  = kk + ((lane >> 4) << 3);
                ldmat_x4(smem_u32(&Ss[row * PQ + ko]),
                         af[mt][0], af[mt][1], af[mt][2], af[mt][3]);
            }
            unsigned bfr[4][2];
#pragma unroll
            for (int nt2 = 0; nt2 < 2; nt2++) {
                int l8 = lane & 7, sel = lane >> 3;
                int kr = kk + ((sel & 1) << 3) + l8;
                int nc = warpN * 32 + nt2 * 16 + ((sel >> 1) << 3);
                unsigned r0, r1, r2, r3;
                ldmat_x4_t(smem_u32(&Vs[kr * PK + nc]), r0, r1, r2, r3);
                bfr[nt2 * 2][0] = r0;     bfr[nt2 * 2][1] = r1;
                bfr[nt2 * 2 + 1][0] = r2; bfr[nt2 * 2 + 1][1] = r3;
            }
#pragma unroll
            for (int mt = 0; mt < 2; mt++)
#pragma unroll
                for (int nt = 0; nt < 4; nt++)
                    mma_bf16(oacc[mt][nt], af[mt], bfr[nt]);
        }
    }

    // store O merged: attn[(b*SEQ + n)*ETOT + h*64 + d]
    const int b = bh >> 4, h = bh & 15;
#pragma unroll
    for (int mt = 0; mt < 2; mt++)
#pragma unroll
        for (int nt = 0; nt < 4; nt++)
#pragma unroll
            for (int r = 0; r < 4; r++) {
                int row = qBase + warpM * 32 + mt * 16 + g + ((r >> 1) << 3);
                int d   = warpN * 32 + nt * 8 + 2 * tig + (r & 1);
                attn[((size_t)b * SEQ + row) * ETOT + h * HDIM + d] = oacc[mt][nt][r];
            }
}

// ---------------- layernorm over E + gate by u ----------------
__global__ __launch_bounds__(256) void ln_gate(
    const float* __restrict__ a, const float* __restrict__ u,
    const float* __restrict__ gamma, const float* __restrict__ beta,
    float* __restrict__ o)
{
    const int row = blockIdx.x;
    const int tid = threadIdx.x;
    const float* ar = a + (size_t)row * ETOT;
    float4 xv = *(const float4*)&ar[tid * 4];

    float s1 = xv.x + xv.y + xv.z + xv.w;
    float s2 = xv.x * xv.x + xv.y * xv.y + xv.z * xv.z + xv.w * xv.w;
#pragma unroll
    for (int o2 = 16; o2 > 0; o2 >>= 1) {
        s1 += __shfl_xor_sync(0xffffffffu, s1, o2);
        s2 += __shfl_xor_sync(0xffffffffu, s2, o2);
    }
    __shared__ float r1[8], r2[8];
    __shared__ float mu_s, inv_s;
    if ((tid & 31) == 0) { r1[tid >> 5] = s1; r2[tid >> 5] = s2; }
    __syncthreads();
    if (tid == 0) {
        float t1 = 0.f, t2 = 0.f;
#pragma unroll
        for (int i = 0; i < 8; i++) { t1 += r1[i]; t2 += r2[i]; }
        float mu = t1 * (1.f / ETOT);
        float var = t2 * (1.f / ETOT) - mu * mu;
        mu_s = mu;
        inv_s = rsqrtf(var + 1e-5f);
    }
    __syncthreads();
    const float mu = mu_s, inv = inv_s;

    float4 gv = *(const float4*)&gamma[tid * 4];
    float4 bv = *(const float4*)&beta[tid * 4];
    float4 uv = *(const float4*)&u[(size_t)row * ETOT + tid * 4];
    float4 ov;
    ov.x = ((xv.x - mu) * inv * gv.x + bv.x) * uv.x;
    ov.y = ((xv.y - mu) * inv * gv.y + bv.y) * uv.y;
    ov.z = ((xv.z - mu) * inv * gv.z + bv.z) * uv.z;
    ov.w = ((xv.w - mu) * inv * gv.w + bv.w) * uv.w;
    *(float4*)&o[(size_t)row * ETOT + tid * 4] = ov;
}

// ---------------- launch ----------------
extern "C" void kernel_launch(void* const* d_in, const int* in_sizes, int n_in,
                              void* d_out, int out_size)
{
    const float* x    = (const float*)d_in[0];
    const float* Wq   = (const float*)d_in[1];
    const float* bq   = (const float*)d_in[2];
    const float* Wk   = (const float*)d_in[3];
    const float* bk   = (const float*)d_in[4];
    const float* Wv   = (const float*)d_in[5];
    const float* bv   = (const float*)d_in[6];
    const float* Wu   = (const float*)d_in[7];
    const float* bu   = (const float*)d_in[8];
    const float* Wo   = (const float*)d_in[9];
    const float* bo   = (const float*)d_in[10];
    const float* ln_g = (const float*)d_in[11];
    const float* ln_b = (const float*)d_in[12];

    float *qp, *kp, *vp, *up, *ap, *gp;
    cudaGetSymbolAddress((void**)&qp, g_q);
    cudaGetSymbolAddress((void**)&kp, g_k);
    cudaGetSymbolAddress((void**)&vp, g_v);
    cudaGetSymbolAddress((void**)&up, g_u);
    cudaGetSymbolAddress((void**)&ap, g_attn);
    cudaGetSymbolAddress((void**)&gp, g_gate);

    cudaFuncSetAttribute(proj_mma,
                         cudaFuncAttributeMaxDynamicSharedMemorySize, PROJ_SMEM);
    cudaFuncSetAttribute(attn_mma,
                         cudaFuncAttributeMaxDynamicSharedMemorySize, ATTN_SMEM);

    dim3 pg(ETOT / 128, MTOT / 128);   // (8, 32)
    proj_mma<<<pg, 256, PROJ_SMEM>>>(x, Wq, bq, qp, 1, 0);
    proj_mma<<<pg, 256, PROJ_SMEM>>>(x, Wk, bk, kp, 1, 0);
    proj_mma<<<pg, 256, PROJ_SMEM>>>(x, Wv, bv, vp, 1, 1);
    proj_mma<<<pg, 256, PROJ_SMEM>>>(x, Wu, bu, up, 0, 1);

    attn_mma<<<dim3(SEQ / 128, 32), 256, ATTN_SMEM>>>(qp, kp, vp, ap);

    ln_gate<<<MTOT, 256>>>(ap, up, ln_g, ln_b, gp);

    proj_mma<<<pg, 256, PROJ_SMEM>>>(gp, Wo, bo, (float*)d_out, 0, 0);
}

// round 3
// speedup vs baseline: 2.8447x; 1.6666x over previous
#include <cuda_runtime.h>
#include <cuda_bf16.h>
#include <math.h>

// Problem dims (fixed)
#define MTOT 4096   // B*N
#define ETOT 1024
#define SEQ  2048
#define NH   16
#define HDIM 64

// ---------------- scratch (device globals) ----------------
__device__ __nv_bfloat16 g_x2[4096 * 2048];        // x split  [4096][hi 1024 | lo 1024]
__device__ __nv_bfloat16 g_w2[5][1024 * 2048];     // W splits [1024][hi|lo] : q,k,v,u,o
__device__ __nv_bfloat16 g_q2[32 * 2048 * 128];    // [bh][n][hi 64 | lo 64]
__device__ __nv_bfloat16 g_k2[32 * 2048 * 128];
__device__ __nv_bfloat16 g_v2[32 * 2048 * 128];
__device__ float g_u[4096 * 1024];
__device__ float g_attn[4096 * 1024];
__device__ __nv_bfloat16 g_g2[4096 * 2048];        // gate split [4096][hi|lo]

// ---------------- helpers ----------------
__device__ __forceinline__ unsigned smem_u32(const void* p) {
    return (unsigned)__cvta_generic_to_shared(p);
}
__device__ __forceinline__ void ldmat_x4(unsigned addr, unsigned* r) {
    asm volatile("ldmatrix.sync.aligned.m8n8.x4.shared.b16 {%0,%1,%2,%3}, [%4];\n"
                 : "=r"(r[0]), "=r"(r[1]), "=r"(r[2]), "=r"(r[3]) : "r"(addr));
}
__device__ __forceinline__ void ldmat_x4_t(unsigned addr, unsigned* r) {
    asm volatile("ldmatrix.sync.aligned.m8n8.x4.trans.shared.b16 {%0,%1,%2,%3}, [%4];\n"
                 : "=r"(r[0]), "=r"(r[1]), "=r"(r[2]), "=r"(r[3]) : "r"(addr));
}
__device__ __forceinline__ void mma_bf16(float* c, const unsigned* a, const unsigned* b) {
    asm volatile(
        "mma.sync.aligned.m16n8k16.row.col.f32.bf16.bf16.f32 "
        "{%0,%1,%2,%3}, {%4,%5,%6,%7}, {%8,%9}, {%0,%1,%2,%3};\n"
        : "+f"(c[0]), "+f"(c[1]), "+f"(c[2]), "+f"(c[3])
        : "r"(a[0]), "r"(a[1]), "r"(a[2]), "r"(a[3]), "r"(b[0]), "r"(b[1]));
}
__device__ __forceinline__ void split_bf16(float x, __nv_bfloat16& hi, __nv_bfloat16& lo) {
    hi = __float2bfloat16(x);
    lo = __float2bfloat16(x - __bfloat162float(hi));
}
__device__ __forceinline__ unsigned pack2(__nv_bfloat16 a, __nv_bfloat16 b) {
    __nv_bfloat162 t; t.x = a; t.y = b;
    return *(unsigned*)&t;
}
__device__ __forceinline__ void cp16(void* dst, const void* src) {
    asm volatile("cp.async.cg.shared.global [%0], [%1], 16;\n"
                 :: "r"(smem_u32(dst)), "l"(src));
}
__device__ __forceinline__ void cp_commit() { asm volatile("cp.async.commit_group;\n"); }
__device__ __forceinline__ void cp_wait0()  { asm volatile("cp.async.wait_group 0;\n" ::: "memory"); }
__device__ __forceinline__ void cp_wait1()  { asm volatile("cp.async.wait_group 1;\n" ::: "memory"); }

// ---------------- split fp32 -> [hi | lo] bf16 ----------------
__global__ __launch_bounds__(256) void split_kernel(
    const float* __restrict__ in, __nv_bfloat16* __restrict__ out,
    int cols, int n4)
{
    int i = blockIdx.x * 256 + threadIdx.x;
    if (i >= n4) return;
    int perRow = cols >> 2;
    int row = i / perRow;
    int c = (i - row * perRow) << 2;
    float4 a = *(const float4*)&in[(size_t)row * cols + c];
    __nv_bfloat16 h0, h1, h2, h3, l0, l1, l2, l3;
    split_bf16(a.x, h0, l0); split_bf16(a.y, h1, l1);
    split_bf16(a.z, h2, l2); split_bf16(a.w, h3, l3);
    uint2 hv; hv.x = pack2(h0, h1); hv.y = pack2(h2, h3);
    uint2 lv; lv.x = pack2(l0, l1); lv.y = pack2(l2, l3);
    *(uint2*)&out[(size_t)row * 2 * cols + c] = hv;
    *(uint2*)&out[(size_t)row * 2 * cols + cols + c] = lv;
}

// ================= projection GEMM (bf16 split inputs, cp.async, dbuf) =================
// C = A @ W^T + bias (+silu). A2 [4096][2048] (hi|lo), W2 [1024][2048] (hi|lo).
// CTA tile 128x128, fp32 K-chunk 32 (= 32 hi + 32 lo bf16).
// mode 0: fp32 [M,E]; mode 1: bf16 split head-split [bh][n][hi64|lo64].
#define PPITCH 72
#define PROJ_SMEM (4 * 128 * PPITCH * 2)   // 2 buffers x (A+B) x 128 x 72 bf16

__device__ __forceinline__ void proj_load(
    const __nv_bfloat16* __restrict__ A2, const __nv_bfloat16* __restrict__ B2,
    __nv_bfloat16* As, __nv_bfloat16* Bs, int mB, int nB, int kb, int tid)
{
#pragma unroll
    for (int t = 0; t < 4; t++) {
        int idx = tid + t * 256;            // 0..1023
        int row = idx >> 3, s = idx & 7;    // 8 x 16B per row (hi 4 + lo 4)
        int gcol = (s < 4) ? (kb + s * 8) : (1024 + kb + (s - 4) * 8);
        int scol = (s < 4) ? (s * 8) : (32 + (s - 4) * 8);
        cp16(&As[row * PPITCH + scol], &A2[(size_t)(mB + row) * 2048 + gcol]);
        cp16(&Bs[row * PPITCH + scol], &B2[(size_t)(nB + row) * 2048 + gcol]);
    }
}

__global__ __launch_bounds__(256) void proj_mma2(
    const __nv_bfloat16* __restrict__ A2, const __nv_bfloat16* __restrict__ W2,
    const float* __restrict__ bias, float* __restrict__ outF,
    __nv_bfloat16* __restrict__ outB, int mode, int act)
{
    extern __shared__ __nv_bfloat16 smb[];
    const int tid = threadIdx.x;
    const int lane = tid & 31, warp = tid >> 5;
    const int warpM = warp >> 1, warpN = warp & 1;
    const int mB = blockIdx.y * 128, nB = blockIdx.x * 128;
    const int g = lane >> 2, tig = lane & 3;

    float acc[2][8][4];
#pragma unroll
    for (int mt = 0; mt < 2; mt++)
#pragma unroll
        for (int nt = 0; nt < 8; nt++)
#pragma unroll
            for (int r = 0; r < 4; r++) acc[mt][nt][r] = 0.f;

    __nv_bfloat16* bufA[2] = { smb, smb + 2 * 128 * PPITCH };
    __nv_bfloat16* bufB[2] = { smb + 128 * PPITCH, smb + 3 * 128 * PPITCH };

    proj_load(A2, W2, bufA[0], bufB[0], mB, nB, 0, tid);
    cp_commit();

    int buf = 0;
    for (int c = 0; c < 32; c++) {
        if (c + 1 < 32) {
            proj_load(A2, W2, bufA[buf ^ 1], bufB[buf ^ 1], mB, nB, (c + 1) * 32, tid);
            cp_commit();
            cp_wait1();
        } else {
            cp_wait0();
        }
        __syncthreads();

        const __nv_bfloat16* As = bufA[buf];
        const __nv_bfloat16* Bs = bufB[buf];
#pragma unroll
        for (int ks = 0; ks < 2; ks++) {
            const int kk = ks * 16;
            unsigned ahi[2][4], alo[2][4];
#pragma unroll
            for (int mt = 0; mt < 2; mt++) {
                int arow = warpM * 32 + mt * 16 + (lane & 15);
                int ako = kk + ((lane >> 4) << 3);
                ldmat_x4(smem_u32(&As[arow * PPITCH + ako]), ahi[mt]);
                ldmat_x4(smem_u32(&As[arow * PPITCH + 32 + ako]), alo[mt]);
            }
#pragma unroll
            for (int p = 0; p < 4; p++) {
                unsigned bh_[4], bl_[4];
                int nrow = warpN * 64 + p * 16 + ((lane >> 4) << 3) + (lane & 7);
                int kc = kk + (((lane >> 3) & 1) << 3);
                ldmat_x4(smem_u32(&Bs[nrow * PPITCH + kc]), bh_);
                ldmat_x4(smem_u32(&Bs[nrow * PPITCH + 32 + kc]), bl_);
#pragma unroll
                for (int mt = 0; mt < 2; mt++) {
                    mma_bf16(acc[mt][2 * p],     ahi[mt], &bh_[0]);
                    mma_bf16(acc[mt][2 * p + 1], ahi[mt], &bh_[2]);
                    mma_bf16(acc[mt][2 * p],     alo[mt], &bh_[0]);
                    mma_bf16(acc[mt][2 * p + 1], alo[mt], &bh_[2]);
                    mma_bf16(acc[mt][2 * p],     ahi[mt], &bl_[0]);
                    mma_bf16(acc[mt][2 * p + 1], ahi[mt], &bl_[2]);
                }
            }
        }
        __syncthreads();
        buf ^= 1;
    }

    // epilogue
#pragma unroll
    for (int mt = 0; mt < 2; mt++)
#pragma unroll
        for (int nt = 0; nt < 8; nt++)
#pragma unroll
            for (int rp = 0; rp < 2; rp++) {
                int m = mB + warpM * 32 + mt * 16 + g + rp * 8;
                int e0 = nB + warpN * 64 + nt * 8 + 2 * tig;
                float v0 = acc[mt][nt][rp * 2]     + bias[e0];
                float v1 = acc[mt][nt][rp * 2 + 1] + bias[e0 + 1];
                if (act) {
                    v0 = v0 / (1.f + __expf(-v0));
                    v1 = v1 / (1.f + __expf(-v1));
                }
                if (mode == 0) {
                    float2 fv; fv.x = v0; fv.y = v1;
                    *(float2*)&outF[(size_t)m * ETOT + e0] = fv;
                } else {
                    int b = m >> 11, n = m & (SEQ - 1);
                    int h = e0 >> 6, d = e0 & (HDIM - 1);
                    __nv_bfloat16 h0, h1, l0, l1;
                    split_bf16(v0, h0, l0);
                    split_bf16(v1, h1, l1);
                    size_t base = (((size_t)b * NH + h) * SEQ + n) * 128 + d;
                    *(unsigned*)&outB[base]      = pack2(h0, h1);
                    *(unsigned*)&outB[base + 64] = pack2(l0, l1);
                }
            }
}

// ================= attention (bf16 split, cp.async) =================
// S = relu(Q K^T / 8), O = S V.  q2/k2/v2: [bh][row][hi64|lo64].
// Tiles: 128 q x 64 keys. Qs/Ss [128][136], Ks [64][136], Vs [128][72].
#define QPITCH 136
#define VPITCH 72
#define ATTN_SMEM ((128 * QPITCH + 128 * QPITCH + 64 * QPITCH + 128 * VPITCH) * 2)

__global__ __launch_bounds__(256) void attn_mma2(
    const __nv_bfloat16* __restrict__ q2, const __nv_bfloat16* __restrict__ k2,
    const __nv_bfloat16* __restrict__ v2, float* __restrict__ attn)
{
    extern __shared__ __nv_bfloat16 smb[];
    __nv_bfloat16* Qs = smb;                            // [128][136]
    __nv_bfloat16* Ss = Qs + 128 * QPITCH;              // [128][136]
    __nv_bfloat16* Ks = Ss + 128 * QPITCH;              // [64][136]
    __nv_bfloat16* Vs = Ks + 64 * QPITCH;               // [128][72] (hi rows 0-63, lo 64-127)

    const int tid = threadIdx.x;
    const int lane = tid & 31, warp = tid >> 5;
    const int warpM = warp >> 1, warpN = warp & 1;
    const int bh = blockIdx.y;
    const int qBase = blockIdx.x * 128;
    const int g = lane >> 2, tig = lane & 3;
    const __nv_bfloat16* qp = q2 + (size_t)bh * SEQ * 128;
    const __nv_bfloat16* kp = k2 + (size_t)bh * SEQ * 128;
    const __nv_bfloat16* vp = v2 + (size_t)bh * SEQ * 128;

    // Q tile (persistent): 128 rows x 256B
#pragma unroll
    for (int t = 0; t < 8; t++) {
        int idx = tid + t * 256;
        int row = idx >> 4, s = idx & 15;
        cp16(&Qs[row * QPITCH + s * 8], &qp[(size_t)(qBase + row) * 128 + s * 8]);
    }
    cp_commit();

    float oacc[2][4][4];
#pragma unroll
    for (int mt = 0; mt < 2; mt++)
#pragma unroll
        for (int nt = 0; nt < 4; nt++)
#pragma unroll
            for (int r = 0; r < 4; r++) oacc[mt][nt][r] = 0.f;

    for (int kt = 0; kt < SEQ; kt += 64) {
        __syncthreads();   // Ks/Vs/Ss free (prev phase3 done)
#pragma unroll
        for (int t = 0; t < 4; t++) {
            int idx = tid + t * 256;           // 0..1023
            int row = idx >> 4, s = idx & 15;
            cp16(&Ks[row * QPITCH + s * 8], &kp[(size_t)(kt + row) * 128 + s * 8]);
            if (s < 8)
                cp16(&Vs[row * VPITCH + s * 8], &vp[(size_t)(kt + row) * 128 + s * 8]);
            else
                cp16(&Vs[(64 + row) * VPITCH + (s - 8) * 8], &vp[(size_t)(kt + row) * 128 + s * 8]);
        }
        cp_commit();
        cp_wait0();
        __syncthreads();

        // ---- phase 2: S = Q K^T ----
        float sacc[2][4][4];
#pragma unroll
        for (int mt = 0; mt < 2; mt++)
#pragma unroll
            for (int nt = 0; nt < 4; nt++)
#pragma unroll
                for (int r = 0; r < 4; r++) sacc[mt][nt][r] = 0.f;

#pragma unroll
        for (int ks = 0; ks < 4; ks++) {
            const int kk = ks * 16;
            unsigned qhi[2][4], qlo[2][4];
#pragma unroll
            for (int mt = 0; mt < 2; mt++) {
                int arow = warpM * 32 + mt * 16 + (lane & 15);
                int ako = kk + ((lane >> 4) << 3);
                ldmat_x4(smem_u32(&Qs[arow * QPITCH + ako]), qhi[mt]);
                ldmat_x4(smem_u32(&Qs[arow * QPITCH + 64 + ako]), qlo[mt]);
            }
#pragma unroll
            for (int p = 0; p < 2; p++) {
                unsigned kh_[4], kl_[4];
                int jrow = warpN * 32 + p * 16 + ((lane >> 4) << 3) + (lane & 7);
                int kc = kk + (((lane >> 3) & 1) << 3);
                ldmat_x4(smem_u32(&Ks[jrow * QPITCH + kc]), kh_);
                ldmat_x4(smem_u32(&Ks[jrow * QPITCH + 64 + kc]), kl_);
#pragma unroll
                for (int mt = 0; mt < 2; mt++) {
                    mma_bf16(sacc[mt][2 * p],     qhi[mt], &kh_[0]);
                    mma_bf16(sacc[mt][2 * p + 1], qhi[mt], &kh_[2]);
                    mma_bf16(sacc[mt][2 * p],     qlo[mt], &kh_[0]);
                    mma_bf16(sacc[mt][2 * p + 1], qlo[mt], &kh_[2]);
                    mma_bf16(sacc[mt][2 * p],     qhi[mt], &kl_[0]);
                    mma_bf16(sacc[mt][2 * p + 1], qhi[mt], &kl_[2]);
                }
            }
        }

        // scale + relu + split into Ss [i][hi64|lo64]
#pragma unroll
        for (int mt = 0; mt < 2; mt++)
#pragma unroll
            for (int nt = 0; nt < 4; nt++)
#pragma unroll
                for (int rp = 0; rp < 2; rp++) {
                    int row = warpM * 32 + mt * 16 + g + rp * 8;
                    int j0 = warpN * 32 + nt * 8 + 2 * tig;
                    float v0 = sacc[mt][nt][rp * 2] * 0.125f;
                    float v1 = sacc[mt][nt][rp * 2 + 1] * 0.125f;
                    v0 = v0 > 0.f ? v0 : 0.f;
                    v1 = v1 > 0.f ? v1 : 0.f;
                    __nv_bfloat16 h0, h1, l0, l1;
                    split_bf16(v0, h0, l0);
                    split_bf16(v1, h1, l1);
                    *(unsigned*)&Ss[row * QPITCH + j0]      = pack2(h0, h1);
                    *(unsigned*)&Ss[row * QPITCH + 64 + j0] = pack2(l0, l1);
                }
        __syncthreads();

        // ---- phase 3: O += S V ----
#pragma unroll
        for (int ks = 0; ks < 4; ks++) {
            const int kk = ks * 16;
            unsigned shi[2][4], slo[2][4];
#pragma unroll
            for (int mt = 0; mt < 2; mt++) {
                int arow = warpM * 32 + mt * 16 + (lane & 15);
                int ako = kk + ((lane >> 4) << 3);
                ldmat_x4(smem_u32(&Ss[arow * QPITCH + ako]), shi[mt]);
                ldmat_x4(smem_u32(&Ss[arow * QPITCH + 64 + ako]), slo[mt]);
            }
            const int sel = lane >> 3, l8 = lane & 7;
#pragma unroll
            for (int p = 0; p < 2; p++) {
                unsigned vh_[4], vl_[4];
                int krh = kk + ((sel & 1) << 3) + l8;
                int nc = warpN * 32 + p * 16 + ((sel >> 1) << 3);
                ldmat_x4_t(smem_u32(&Vs[krh * VPITCH + nc]), vh_);
                ldmat_x4_t(smem_u32(&Vs[(64 + krh) * VPITCH + nc]), vl_);
#pragma unroll
                for (int mt = 0; mt < 2; mt++) {
                    mma_bf16(oacc[mt][2 * p],     shi[mt], &vh_[0]);
                    mma_bf16(oacc[mt][2 * p + 1], shi[mt], &vh_[2]);
                    mma_bf16(oacc[mt][2 * p],     slo[mt], &vh_[0]);
                    mma_bf16(oacc[mt][2 * p + 1], slo[mt], &vh_[2]);
                    mma_bf16(oacc[mt][2 * p],     shi[mt], &vl_[0]);
                    mma_bf16(oacc[mt][2 * p + 1], shi[mt], &vl_[2]);
                }
            }
        }
    }

    // store O merged fp32: attn[(b*SEQ+n)*ETOT + h*64 + d]
    const int b = bh >> 4, h = bh & 15;
#pragma unroll
    for (int mt = 0; mt < 2; mt++)
#pragma unroll
        for (int nt = 0; nt < 4; nt++)
#pragma unroll
            for (int rp = 0; rp < 2; rp++) {
                int row = qBase + warpM * 32 + mt * 16 + g + rp * 8;
                int d0 = warpN * 32 + nt * 8 + 2 * tig;
                float2 fv;
                fv.x = oacc[mt][nt][rp * 2];
                fv.y = oacc[mt][nt][rp * 2 + 1];
                *(float2*)&attn[((size_t)b * SEQ + row) * ETOT + h * HDIM + d0] = fv;
            }
}

// ---------------- layernorm + gate; writes split bf16 gate ----------------
__global__ __launch_bounds__(256) void ln_gate(
    const float* __restrict__ a, const float* __restrict__ u,
    const float* __restrict__ gamma, const float* __restrict__ beta,
    __nv_bfloat16* __restrict__ o2)
{
    const int row = blockIdx.x;
    const int tid = threadIdx.x;
    const float* ar = a + (size_t)row * ETOT;
    float4 xv = *(const float4*)&ar[tid * 4];

    float s1 = xv.x + xv.y + xv.z + xv.w;
    float s2 = xv.x * xv.x + xv.y * xv.y + xv.z * xv.z + xv.w * xv.w;
#pragma unroll
    for (int o = 16; o > 0; o >>= 1) {
        s1 += __shfl_xor_sync(0xffffffffu, s1, o);
        s2 += __shfl_xor_sync(0xffffffffu, s2, o);
    }
    __shared__ float r1[8], r2[8];
    __shared__ float mu_s, inv_s;
    if ((tid & 31) == 0) { r1[tid >> 5] = s1; r2[tid >> 5] = s2; }
    __syncthreads();
    if (tid == 0) {
        float t1 = 0.f, t2 = 0.f;
#pragma unroll
        for (int i = 0; i < 8; i++) { t1 += r1[i]; t2 += r2[i]; }
        float mu = t1 * (1.f / ETOT);
        float var = t2 * (1.f / ETOT) - mu * mu;
        mu_s = mu;
        inv_s = rsqrtf(var + 1e-5f);
    }
    __syncthreads();
    const float mu = mu_s, inv = inv_s;

    float4 gv = *(const float4*)&gamma[tid * 4];
    float4 bv = *(const float4*)&beta[tid * 4];
    float4 uv = *(const float4*)&u[(size_t)row * ETOT + tid * 4];
    float o0 = ((xv.x - mu) * inv * gv.x + bv.x) * uv.x;
    float o1 = ((xv.y - mu) * inv * gv.y + bv.y) * uv.y;
    float o2v = ((xv.z - mu) * inv * gv.z + bv.z) * uv.z;
    float o3 = ((xv.w - mu) * inv * gv.w + bv.w) * uv.w;
    __nv_bfloat16 h0, h1, h2, h3, l0, l1, l2, l3;
    split_bf16(o0, h0, l0); split_bf16(o1, h1, l1);
    split_bf16(o2v, h2, l2); split_bf16(o3, h3, l3);
    uint2 hv; hv.x = pack2(h0, h1); hv.y = pack2(h2, h3);
    uint2 lv; lv.x = pack2(l0, l1); lv.y = pack2(l2, l3);
    *(uint2*)&o2[(size_t)row * 2048 + tid * 4]        = hv;
    *(uint2*)&o2[(size_t)row * 2048 + 1024 + tid * 4] = lv;
}

// ---------------- launch ----------------
extern "C" void kernel_launch(void* const* d_in, const int* in_sizes, int n_in,
                              void* d_out, int out_size)
{
    const float* x    = (const float*)d_in[0];
    const float* Wq   = (const float*)d_in[1];
    const float* bq   = (const float*)d_in[2];
    const float* Wk   = (const float*)d_in[3];
    const float* bk   = (const float*)d_in[4];
    const float* Wv   = (const float*)d_in[5];
    const float* bv   = (const float*)d_in[6];
    const float* Wu   = (const float*)d_in[7];
    const float* bu   = (const float*)d_in[8];
    const float* Wo   = (const float*)d_in[9];
    const float* bo   = (const float*)d_in[10];
    const float* ln_g = (const float*)d_in[11];
    const float* ln_b = (const float*)d_in[12];

    __nv_bfloat16 *x2, *w2, *q2, *k2, *v2, *g2;
    float *up, *ap;
    cudaGetSymbolAddress((void**)&x2, g_x2);
    cudaGetSymbolAddress((void**)&w2, g_w2);
    cudaGetSymbolAddress((void**)&q2, g_q2);
    cudaGetSymbolAddress((void**)&k2, g_k2);
    cudaGetSymbolAddress((void**)&v2, g_v2);
    cudaGetSymbolAddress((void**)&up, g_u);
    cudaGetSymbolAddress((void**)&ap, g_attn);
    cudaGetSymbolAddress((void**)&g2, g_g2);

    __nv_bfloat16* w2q = w2;
    __nv_bfloat16* w2k = w2 + (size_t)1 * 1024 * 2048;
    __nv_bfloat16* w2v = w2 + (size_t)2 * 1024 * 2048;
    __nv_bfloat16* w2u = w2 + (size_t)3 * 1024 * 2048;
    __nv_bfloat16* w2o = w2 + (size_t)4 * 1024 * 2048;

    cudaFuncSetAttribute(proj_mma2,
                         cudaFuncAttributeMaxDynamicSharedMemorySize, PROJ_SMEM);
    cudaFuncSetAttribute(attn_mma2,
                         cudaFuncAttributeMaxDynamicSharedMemorySize, ATTN_SMEM);

    // splits
    split_kernel<<<4096, 256>>>(x, x2, 1024, 4096 * 1024 / 4);
    split_kernel<<<1024, 256>>>(Wq, w2q, 1024, 1024 * 1024 / 4);
    split_kernel<<<1024, 256>>>(Wk, w2k, 1024, 1024 * 1024 / 4);
    split_kernel<<<1024, 256>>>(Wv, w2v, 1024, 1024 * 1024 / 4);
    split_kernel<<<1024, 256>>>(Wu, w2u, 1024, 1024 * 1024 / 4);
    split_kernel<<<1024, 256>>>(Wo, w2o, 1024, 1024 * 1024 / 4);

    dim3 pg(ETOT / 128, MTOT / 128);   // (8, 32)
    proj_mma2<<<pg, 256, PROJ_SMEM>>>(x2, w2q, bq, nullptr, q2, 1, 0);
    proj_mma2<<<pg, 256, PROJ_SMEM>>>(x2, w2k, bk, nullptr, k2, 1, 0);
    proj_mma2<<<pg, 256, PROJ_SMEM>>>(x2, w2v, bv, nullptr, v2, 1, 1);
    proj_mma2<<<pg, 256, PROJ_SMEM>>>(x2, w2u, bu, up, nullptr, 0, 1);

    attn_mma2<<<dim3(SEQ / 128, 32), 256, ATTN_SMEM>>>(q2, k2, v2, ap);

    ln_gate<<<MTOT, 256>>>(ap, up, ln_g, ln_b, g2);

    proj_mma2<<<pg, 256, PROJ_SMEM>>>(g2, w2o, bo, (float*)d_out, nullptr, 0, 0);
}

// round 7
// speedup vs baseline: 3.0621x; 1.0764x over previous
#include <cuda_runtime.h>
#include <cuda_bf16.h>
#include <stdint.h>
#include <math.h>

// Problem dims (fixed)
#define MTOT 4096   // B*N
#define ETOT 1024
#define SEQ  2048
#define NH   16
#define HDIM 64

// ---------------- scratch (device globals) ----------------
__device__ __nv_bfloat16 g_x2[4096 * 2048];        // x split  [4096][hi 1024 | lo 1024]
__device__ __nv_bfloat16 g_w5[5120 * 2048];        // W splits packed rows: q,k,v,u,o
__device__ __nv_bfloat16 g_g2[4096 * 2048];        // gate split [hi|lo]
__device__ __nv_bfloat16 g_q2[32 * 2048 * 128];    // [bh][n][hi 64 | lo 64]
__device__ __nv_bfloat16 g_k2[32 * 2048 * 128];
__device__ __nv_bfloat16 g_v2[32 * 2048 * 128];
__device__ float g_u[4096 * 1024];
__device__ float g_attn[4096 * 1024];

// ---------------- helpers ----------------
__device__ __forceinline__ unsigned smem_u32(const void* p) {
    return (unsigned)__cvta_generic_to_shared(p);
}
__device__ __forceinline__ void ldmat_x4(unsigned addr, unsigned* r) {
    asm volatile("ldmatrix.sync.aligned.m8n8.x4.shared.b16 {%0,%1,%2,%3}, [%4];\n"
                 : "=r"(r[0]), "=r"(r[1]), "=r"(r[2]), "=r"(r[3]) : "r"(addr));
}
__device__ __forceinline__ void ldmat_x4_t(unsigned addr, unsigned* r) {
    asm volatile("ldmatrix.sync.aligned.m8n8.x4.trans.shared.b16 {%0,%1,%2,%3}, [%4];\n"
                 : "=r"(r[0]), "=r"(r[1]), "=r"(r[2]), "=r"(r[3]) : "r"(addr));
}
__device__ __forceinline__ void mma_bf16(float* c, const unsigned* a, const unsigned* b) {
    asm volatile(
        "mma.sync.aligned.m16n8k16.row.col.f32.bf16.bf16.f32 "
        "{%0,%1,%2,%3}, {%4,%5,%6,%7}, {%8,%9}, {%0,%1,%2,%3};\n"
        : "+f"(c[0]), "+f"(c[1]), "+f"(c[2]), "+f"(c[3])
        : "r"(a[0]), "r"(a[1]), "r"(a[2]), "r"(a[3]), "r"(b[0]), "r"(b[1]));
}
__device__ __forceinline__ void split_bf16(float x, __nv_bfloat16& hi, __nv_bfloat16& lo) {
    hi = __float2bfloat16(x);
    lo = __float2bfloat16(x - __bfloat162float(hi));
}
__device__ __forceinline__ unsigned pack2(__nv_bfloat16 a, __nv_bfloat16 b) {
    __nv_bfloat162 t; t.x = a; t.y = b;
    return *(unsigned*)&t;
}
__device__ __forceinline__ void cp16(unsigned dst, const void* src) {
    asm volatile("cp.async.cg.shared.global [%0], [%1], 16;\n" :: "r"(dst), "l"(src));
}
__device__ __forceinline__ void cp_commit() { asm volatile("cp.async.commit_group;\n"); }
__device__ __forceinline__ void cp_wait0()  { asm volatile("cp.async.wait_group 0;\n" ::: "memory"); }
__device__ __forceinline__ void cp_wait1()  { asm volatile("cp.async.wait_group 1;\n" ::: "memory"); }
__device__ __forceinline__ void cp_wait2()  { asm volatile("cp.async.wait_group 2;\n" ::: "memory"); }

// ---------------- split fp32 -> [hi | lo] bf16 (single src) ----------------
__global__ __launch_bounds__(256) void split_kernel(
    const float* __restrict__ in, __nv_bfloat16* __restrict__ out, int n4)
{
    int i = blockIdx.x * 256 + threadIdx.x;
    if (i >= n4) return;
    int row = i >> 8;              // 1024 cols / 4
    int c = (i & 255) << 2;
    float4 a = *(const float4*)&in[(size_t)row * 1024 + c];
    __nv_bfloat16 h0, h1, h2, h3, l0, l1, l2, l3;
    split_bf16(a.x, h0, l0); split_bf16(a.y, h1, l1);
    split_bf16(a.z, h2, l2); split_bf16(a.w, h3, l3);
    uint2 hv; hv.x = pack2(h0, h1); hv.y = pack2(h2, h3);
    uint2 lv; lv.x = pack2(l0, l1); lv.y = pack2(l2, l3);
    *(uint2*)&out[(size_t)row * 2048 + c] = hv;
    *(uint2*)&out[(size_t)row * 2048 + 1024 + c] = lv;
}

// ---------------- batched weight split: 5 matrices -> g_w5 ----------------
__global__ __launch_bounds__(256) void splitW_kernel(
    const float* __restrict__ w0, const float* __restrict__ w1,
    const float* __restrict__ w2, const float* __restrict__ w3,
    const float* __restrict__ w4, __nv_bfloat16* __restrict__ out)
{
    int i = blockIdx.x * 256 + threadIdx.x;   // over 5120*1024/4
    int row = i >> 8;                         // 0..5119
    int c = (i & 255) << 2;
    int which = row >> 10;
    int r = row & 1023;
    const float* src = (which == 0) ? w0 : (which == 1) ? w1 :
                       (which == 2) ? w2 : (which == 3) ? w3 : w4;
    float4 a = *(const float4*)&src[(size_t)r * 1024 + c];
    __nv_bfloat16 h0, h1, h2, h3, l0, l1, l2, l3;
    split_bf16(a.x, h0, l0); split_bf16(a.y, h1, l1);
    split_bf16(a.z, h2, l2); split_bf16(a.w, h3, l3);
    uint2 hv; hv.x = pack2(h0, h1); hv.y = pack2(h2, h3);
    uint2 lv; lv.x = pack2(l0, l1); lv.y = pack2(l2, l3);
    *(uint2*)&out[(size_t)row * 2048 + c] = hv;
    *(uint2*)&out[(size_t)row * 2048 + 1024 + c] = lv;
}

// ================= projection GEMM core (3-stage cp.async, HMMA 3-term) =================
#define PPITCH 72
#define PSTG_ELEM (2 * 128 * PPITCH)          // bf16 elems per stage (A+B)
#define PROJ_SMEM (3 * PSTG_ELEM * 2)

// load one K-chunk (32 fp32 cols = [hi32|lo32] bf16) of A and B into stage.
// Each idx covers one 16B slice of BOTH A and B rows (full 64 bf16/row each).
__device__ __forceinline__ void proj_load_chunk(
    const __nv_bfloat16* __restrict__ A2, const __nv_bfloat16* __restrict__ B2,
    __nv_bfloat16* As, __nv_bfloat16* Bs, int mB, int nB, int kb, int tid)
{
#pragma unroll
    for (int t = 0; t < 4; t++) {
        int idx = tid + t * 256;            // 0..1023
        int row = idx >> 3, s = idx & 7;    // 8 x 16B slices per row
        int gcol = (s < 4) ? (kb + s * 8) : (1024 + kb + (s - 4) * 8);
        int scol = (s < 4) ? (s * 8) : (32 + (s - 4) * 8);
        cp16(smem_u32(&As[row * PPITCH + scol]), &A2[(size_t)(mB + row) * 2048 + gcol]);
        cp16(smem_u32(&Bs[row * PPITCH + scol]), &B2[(size_t)(nB + row) * 2048 + gcol]);
    }
}

// mainloop computing acc[2][8][4]; A2/B2 row-major [rows][2048] split bf16
__device__ __forceinline__ void proj_mainloop(
    const __nv_bfloat16* __restrict__ A2, const __nv_bfloat16* __restrict__ B2,
    __nv_bfloat16* smb, int mB, int nB, int tid, int lane,
    int warpM, int warpN, float acc[2][8][4])
{
#pragma unroll
    for (int mt = 0; mt < 2; mt++)
#pragma unroll
        for (int nt = 0; nt < 8; nt++)
#pragma unroll
            for (int r = 0; r < 4; r++) acc[mt][nt][r] = 0.f;

    __nv_bfloat16* stA[3] = { smb, smb + PSTG_ELEM, smb + 2 * PSTG_ELEM };
    proj_load_chunk(A2, B2, stA[0], stA[0] + 128 * PPITCH, mB, nB, 0, tid);
    cp_commit();
    proj_load_chunk(A2, B2, stA[1], stA[1] + 128 * PPITCH, mB, nB, 32, tid);
    cp_commit();

    for (int c = 0; c < 32; c++) {
        if (c + 2 < 32) {
            __nv_bfloat16* st = stA[(c + 2) % 3];
            proj_load_chunk(A2, B2, st, st + 128 * PPITCH, mB, nB, (c + 2) * 32, tid);
            cp_commit();
            cp_wait2();
        } else if (c + 1 < 32) {
            cp_wait1();
        } else {
            cp_wait0();
        }
        __syncthreads();

        const __nv_bfloat16* As = stA[c % 3];
        const __nv_bfloat16* Bs = As + 128 * PPITCH;
#pragma unroll
        for (int ks = 0; ks < 2; ks++) {
            const int kk = ks * 16;
            unsigned ahi[2][4], alo[2][4];
#pragma unroll
            for (int mt = 0; mt < 2; mt++) {
                int arow = warpM * 32 + mt * 16 + (lane & 15);
                int ako = kk + ((lane >> 4) << 3);
                ldmat_x4(smem_u32(&As[arow * PPITCH + ako]), ahi[mt]);
                ldmat_x4(smem_u32(&As[arow * PPITCH + 32 + ako]), alo[mt]);
            }
#pragma unroll
            for (int p = 0; p < 4; p++) {
                unsigned bh_[4], bl_[4];
                int nrow = warpN * 64 + p * 16 + ((lane >> 4) << 3) + (lane & 7);
                int kc = kk + (((lane >> 3) & 1) << 3);
                ldmat_x4(smem_u32(&Bs[nrow * PPITCH + kc]), bh_);
                ldmat_x4(smem_u32(&Bs[nrow * PPITCH + 32 + kc]), bl_);
                // products-outer: RAW distance 4 on each accumulator
#pragma unroll
                for (int mt = 0; mt < 2; mt++) {
                    mma_bf16(acc[mt][2 * p],     ahi[mt], &bh_[0]);
                    mma_bf16(acc[mt][2 * p + 1], ahi[mt], &bh_[2]);
                }
#pragma unroll
                for (int mt = 0; mt < 2; mt++) {
                    mma_bf16(acc[mt][2 * p],     alo[mt], &bh_[0]);
                    mma_bf16(acc[mt][2 * p + 1], alo[mt], &bh_[2]);
                }
#pragma unroll
                for (int mt = 0; mt < 2; mt++) {
                    mma_bf16(acc[mt][2 * p],     ahi[mt], &bl_[0]);
                    mma_bf16(acc[mt][2 * p + 1], ahi[mt], &bl_[2]);
                }
            }
        }
        __syncthreads();
    }
}

// ---- fused Q/K/V/U projection: W rows [0,4096) of g_w5, grid (32,32) ----
__global__ __launch_bounds__(256) void proj_fused(
    const __nv_bfloat16* __restrict__ A2, const __nv_bfloat16* __restrict__ W2,
    const float* __restrict__ b0, const float* __restrict__ b1,
    const float* __restrict__ b2, const float* __restrict__ b3,
    __nv_bfloat16* __restrict__ outQ, __nv_bfloat16* __restrict__ outK,
    __nv_bfloat16* __restrict__ outV, float* __restrict__ outU)
{
    extern __shared__ __nv_bfloat16 smb[];
    const int tid = threadIdx.x;
    const int lane = tid & 31, warp = tid >> 5;
    const int warpM = warp >> 1, warpN = warp & 1;
    const int mB = blockIdx.y * 128, nB = blockIdx.x * 128;
    const int g = lane >> 2, tig = lane & 3;
    const int which = nB >> 10;

    float acc[2][8][4];
    proj_mainloop(A2, W2, smb, mB, nB, tid, lane, warpM, warpN, acc);

    const float* bp = (which == 0) ? b0 : (which == 1) ? b1 : (which == 2) ? b2 : b3;
    __nv_bfloat16* outH = (which == 0) ? outQ : (which == 1) ? outK : outV;
    const int act = (which >= 2);

#pragma unroll
    for (int mt = 0; mt < 2; mt++)
#pragma unroll
        for (int nt = 0; nt < 8; nt++)
#pragma unroll
            for (int rp = 0; rp < 2; rp++) {
                int m = mB + warpM * 32 + mt * 16 + g + rp * 8;
                int e0 = nB + warpN * 64 + nt * 8 + 2 * tig;
                int eq = e0 & 1023;
                float v0 = acc[mt][nt][rp * 2]     + __ldg(&bp[eq]);
                float v1 = acc[mt][nt][rp * 2 + 1] + __ldg(&bp[eq + 1]);
                if (act) {
                    v0 = v0 / (1.f + __expf(-v0));
                    v1 = v1 / (1.f + __expf(-v1));
                }
                if (which == 3) {
                    float2 fv; fv.x = v0; fv.y = v1;
                    *(float2*)&outU[(size_t)m * ETOT + eq] = fv;
                } else {
                    int b = m >> 11, n = m & (SEQ - 1);
                    int h = eq >> 6, d = eq & (HDIM - 1);
                    __nv_bfloat16 h0, h1, l0, l1;
                    split_bf16(v0, h0, l0);
                    split_bf16(v1, h1, l1);
                    size_t base = (((size_t)b * NH + h) * SEQ + n) * 128 + d;
                    *(unsigned*)&outH[base]      = pack2(h0, h1);
                    *(unsigned*)&outH[base + 64] = pack2(l0, l1);
                }
            }
}

// ---- output projection: gate @ Wo^T + bo -> fp32 d_out, grid (8,32) ----
__global__ __launch_bounds__(256) void proj_out(
    const __nv_bfloat16* __restrict__ A2, const __nv_bfloat16* __restrict__ W2,
    const float* __restrict__ bias, float* __restrict__ outF)
{
    extern __shared__ __nv_bfloat16 smb[];
    const int tid = threadIdx.x;
    const int lane = tid & 31, warp = tid >> 5;
    const int warpM = warp >> 1, warpN = warp & 1;
    const int mB = blockIdx.y * 128, nB = blockIdx.x * 128;
    const int g = lane >> 2, tig = lane & 3;

    float acc[2][8][4];
    proj_mainloop(A2, W2, smb, mB, nB, tid, lane, warpM, warpN, acc);

#pragma unroll
    for (int mt = 0; mt < 2; mt++)
#pragma unroll
        for (int nt = 0; nt < 8; nt++)
#pragma unroll
            for (int rp = 0; rp < 2; rp++) {
                int m = mB + warpM * 32 + mt * 16 + g + rp * 8;
                int e0 = nB + warpN * 64 + nt * 8 + 2 * tig;
                float2 fv;
                fv.x = acc[mt][nt][rp * 2]     + __ldg(&bias[e0]);
                fv.y = acc[mt][nt][rp * 2 + 1] + __ldg(&bias[e0 + 1]);
                *(float2*)&outF[(size_t)m * ETOT + e0] = fv;
            }
}

// ================= attention (HMMA 3-term, split waits for overlap) =================
#define QPITCH 136
#define VPITCH 72
#define ATTN_SMEM ((128 * QPITCH + 128 * QPITCH + 64 * QPITCH + 128 * VPITCH) * 2)

__device__ __forceinline__ void attn_load_k(
    const __nv_bfloat16* kp, __nv_bfloat16* Ks, int kt, int tid)
{
#pragma unroll
    for (int t = 0; t < 4; t++) {
        int idx = tid + t * 256;
        int row = idx >> 4, s = idx & 15;
        cp16(smem_u32(&Ks[row * QPITCH + s * 8]), &kp[(size_t)(kt + row) * 128 + s * 8]);
    }
}
__device__ __forceinline__ void attn_load_v(
    const __nv_bfloat16* vp, __nv_bfloat16* Vs, int kt, int tid)
{
#pragma unroll
    for (int t = 0; t < 4; t++) {
        int idx = tid + t * 256;
        int row = idx >> 4, s = idx & 15;
        if (s < 8)
            cp16(smem_u32(&Vs[row * VPITCH + s * 8]), &vp[(size_t)(kt + row) * 128 + s * 8]);
        else
            cp16(smem_u32(&Vs[(64 + row) * VPITCH + (s - 8) * 8]),
                 &vp[(size_t)(kt + row) * 128 + s * 8]);
    }
}

__global__ __launch_bounds__(256) void attn_mma2(
    const __nv_bfloat16* __restrict__ q2, const __nv_bfloat16* __restrict__ k2,
    const __nv_bfloat16* __restrict__ v2, float* __restrict__ attn)
{
    extern __shared__ __nv_bfloat16 smb[];
    __nv_bfloat16* Qs = smb;
    __nv_bfloat16* Ss = Qs + 128 * QPITCH;
    __nv_bfloat16* Ks = Ss + 128 * QPITCH;
    __nv_bfloat16* Vs = Ks + 64 * QPITCH;

    const int tid = threadIdx.x;
    const int lane = tid & 31, warp = tid >> 5;
    const int warpM = warp >> 1, warpN = warp & 1;
    const int bh = blockIdx.y;
    const int qBase = blockIdx.x * 128;
    const int g = lane >> 2, tig = lane & 3;
    const __nv_bfloat16* qp = q2 + (size_t)bh * SEQ * 128;
    const __nv_bfloat16* kp = k2 + (size_t)bh * SEQ * 128;
    const __nv_bfloat16* vp = v2 + (size_t)bh * SEQ * 128;

    // Q (persistent), then K0, V0 — three commit groups in FIFO order
#pragma unroll
    for (int t = 0; t < 8; t++) {
        int idx = tid + t * 256;
        int row = idx >> 4, s = idx & 15;
        cp16(smem_u32(&Qs[row * QPITCH + s * 8]), &qp[(size_t)(qBase + row) * 128 + s * 8]);
    }
    cp_commit();
    attn_load_k(kp, Ks, 0, tid);
    cp_commit();
    attn_load_v(vp, Vs, 0, tid);
    cp_commit();

    float oacc[2][4][4];
#pragma unroll
    for (int mt = 0; mt < 2; mt++)
#pragma unroll
        for (int nt = 0; nt < 4; nt++)
#pragma unroll
            for (int r = 0; r < 4; r++) oacc[mt][nt][r] = 0.f;

    for (int kt = 0; kt < SEQ; kt += 64) {
        const bool hasNext = (kt + 64 < SEQ);
        // need Q + K_i done; V_i may still be in flight
        cp_wait1();
        __syncthreads();

        // ---- phase 2: S = Q K^T ----
        float sacc[2][4][4];
#pragma unroll
        for (int mt = 0; mt < 2; mt++)
#pragma unroll
            for (int nt = 0; nt < 4; nt++)
#pragma unroll
                for (int r = 0; r < 4; r++) sacc[mt][nt][r] = 0.f;

#pragma unroll
        for (int ks = 0; ks < 4; ks++) {
            const int kk = ks * 16;
            unsigned qhi[2][4], qlo[2][4];
#pragma unroll
            for (int mt = 0; mt < 2; mt++) {
                int arow = warpM * 32 + mt * 16 + (lane & 15);
                int ako = kk + ((lane >> 4) << 3);
                ldmat_x4(smem_u32(&Qs[arow * QPITCH + ako]), qhi[mt]);
                ldmat_x4(smem_u32(&Qs[arow * QPITCH + 64 + ako]), qlo[mt]);
            }
#pragma unroll
            for (int p = 0; p < 2; p++) {
                unsigned kh_[4], kl_[4];
                int jrow = warpN * 32 + p * 16 + ((lane >> 4) << 3) + (lane & 7);
                int kc = kk + (((lane >> 3) & 1) << 3);
                ldmat_x4(smem_u32(&Ks[jrow * QPITCH + kc]), kh_);
                ldmat_x4(smem_u32(&Ks[jrow * QPITCH + 64 + kc]), kl_);
#pragma unroll
                for (int mt = 0; mt < 2; mt++) {
                    mma_bf16(sacc[mt][2 * p],     qhi[mt], &kh_[0]);
                    mma_bf16(sacc[mt][2 * p + 1], qhi[mt], &kh_[2]);
                }
#pragma unroll
                for (int mt = 0; mt < 2; mt++) {
                    mma_bf16(sacc[mt][2 * p],     qlo[mt], &kh_[0]);
                    mma_bf16(sacc[mt][2 * p + 1], qlo[mt], &kh_[2]);
                }
#pragma unroll
                for (int mt = 0; mt < 2; mt++) {
                    mma_bf16(sacc[mt][2 * p],     qhi[mt], &kl_[0]);
                    mma_bf16(sacc[mt][2 * p + 1], qhi[mt], &kl_[2]);
                }
            }
        }

        // scale + relu + split into Ss [i][hi64|lo64]
#pragma unroll
        for (int mt = 0; mt < 2; mt++)
#pragma unroll
            for (int nt = 0; nt < 4; nt++)
#pragma unroll
                for (int rp = 0; rp < 2; rp++) {
                    int row = warpM * 32 + mt * 16 + g + rp * 8;
                    int j0 = warpN * 32 + nt * 8 + 2 * tig;
                    float v0 = sacc[mt][nt][rp * 2] * 0.125f;
                    float v1 = sacc[mt][nt][rp * 2 + 1] * 0.125f;
                    v0 = v0 > 0.f ? v0 : 0.f;
                    v1 = v1 > 0.f ? v1 : 0.f;
                    __nv_bfloat16 h0, h1, l0, l1;
                    split_bf16(v0, h0, l0);
                    split_bf16(v1, h1, l1);
                    *(unsigned*)&Ss[row * QPITCH + j0]      = pack2(h0, h1);
                    *(unsigned*)&Ss[row * QPITCH + 64 + j0] = pack2(l0, l1);
                }
        __syncthreads();   // all warps done reading Ks (phase2) and writing Ss

        // issue next K tile load — overlaps phase 3 compute
        if (hasNext) {
            attn_load_k(kp, Ks, kt + 64, tid);
            cp_commit();
            cp_wait1();    // V_i done; next-K may stay in flight
        } else {
            cp_wait0();    // tail: nothing else pending — V_last must be complete
        }

        // ---- phase 3: O += S V ----
#pragma unroll
        for (int ks = 0; ks < 4; ks++) {
            const int kk = ks * 16;
            unsigned shi[2][4], slo[2][4];
#pragma unroll
            for (int mt = 0; mt < 2; mt++) {
                int arow = warpM * 32 + mt * 16 + (lane & 15);
                int ako = kk + ((lane >> 4) << 3);
                ldmat_x4(smem_u32(&Ss[arow * QPITCH + ako]), shi[mt]);
                ldmat_x4(smem_u32(&Ss[arow * QPITCH + 64 + ako]), slo[mt]);
            }
            const int sel = lane >> 3, l8 = lane & 7;
#pragma unroll
            for (int p = 0; p < 2; p++) {
                unsigned vh_[4], vl_[4];
                int krh = kk + ((sel & 1) << 3) + l8;
                int nc = warpN * 32 + p * 16 + ((sel >> 1) << 3);
                ldmat_x4_t(smem_u32(&Vs[krh * VPITCH + nc]), vh_);
                ldmat_x4_t(smem_u32(&Vs[(64 + krh) * VPITCH + nc]), vl_);
#pragma unroll
                for (int mt = 0; mt < 2; mt++) {
                    mma_bf16(oacc[mt][2 * p],     shi[mt], &vh_[0]);
                    mma_bf16(oacc[mt][2 * p + 1], shi[mt], &vh_[2]);
                }
#pragma unroll
                for (int mt = 0; mt < 2; mt++) {
                    mma_bf16(oacc[mt][2 * p],     slo[mt], &vh_[0]);
                    mma_bf16(oacc[mt][2 * p + 1], slo[mt], &vh_[2]);
                }
#pragma unroll
                for (int mt = 0; mt < 2; mt++) {
                    mma_bf16(oacc[mt][2 * p],     shi[mt], &vl_[0]);
                    mma_bf16(oacc[mt][2 * p + 1], shi[mt], &vl_[2]);
                }
            }
        }
        __syncthreads();   // all warps done reading Vs + Ss

        // issue next V tile load — overlaps next phase 2
        if (hasNext) {
            attn_load_v(vp, Vs, kt + 64, tid);
            cp_commit();
        }
    }

    const int b = bh >> 4, h = bh & 15;
#pragma unroll
    for (int mt = 0; mt < 2; mt++)
#pragma unroll
        for (int nt = 0; nt < 4; nt++)
#pragma unroll
            for (int rp = 0; rp < 2; rp++) {
                int row = qBase + warpM * 32 + mt * 16 + g + rp * 8;
                int d0 = warpN * 32 + nt * 8 + 2 * tig;
                float2 fv;
                fv.x = oacc[mt][nt][rp * 2];
                fv.y = oacc[mt][nt][rp * 2 + 1];
                *(float2*)&attn[((size_t)b * SEQ + row) * ETOT + h * HDIM + d0] = fv;
            }
}

// ---------------- layernorm + gate; writes split bf16 gate ----------------
__global__ __launch_bounds__(256) void ln_gate(
    const float* __restrict__ a, const float* __restrict__ u,
    const float* __restrict__ gamma, const float* __restrict__ beta,
    __nv_bfloat16* __restrict__ o2)
{
    const int row = blockIdx.x;
    const int tid = threadIdx.x;
    const float* ar = a + (size_t)row * ETOT;
    float4 xv = *(const float4*)&ar[tid * 4];

    float s1 = xv.x + xv.y + xv.z + xv.w;
    float s2 = xv.x * xv.x + xv.y * xv.y + xv.z * xv.z + xv.w * xv.w;
#pragma unroll
    for (int o = 16; o > 0; o >>= 1) {
        s1 += __shfl_xor_sync(0xffffffffu, s1, o);
        s2 += __shfl_xor_sync(0xffffffffu, s2, o);
    }
    __shared__ float r1[8], r2[8];
    __shared__ float mu_s, inv_s;
    if ((tid & 31) == 0) { r1[tid >> 5] = s1; r2[tid >> 5] = s2; }
    __syncthreads();
    if (tid == 0) {
        float t1 = 0.f, t2 = 0.f;
#pragma unroll
        for (int i = 0; i < 8; i++) { t1 += r1[i]; t2 += r2[i]; }
        float mu = t1 * (1.f / ETOT);
        float var = t2 * (1.f / ETOT) - mu * mu;
        mu_s = mu;
        inv_s = rsqrtf(var + 1e-5f);
    }
    __syncthreads();
    const float mu = mu_s, inv = inv_s;

    float4 gv = *(const float4*)&gamma[tid * 4];
    float4 bv = *(const float4*)&beta[tid * 4];
    float4 uv = *(const float4*)&u[(size_t)row * ETOT + tid * 4];
    float o0 = ((xv.x - mu) * inv * gv.x + bv.x) * uv.x;
    float o1 = ((xv.y - mu) * inv * gv.y + bv.y) * uv.y;
    float o2v = ((xv.z - mu) * inv * gv.z + bv.z) * uv.z;
    float o3 = ((xv.w - mu) * inv * gv.w + bv.w) * uv.w;
    __nv_bfloat16 h0, h1, h2, h3, l0, l1, l2, l3;
    split_bf16(o0, h0, l0); split_bf16(o1, h1, l1);
    split_bf16(o2v, h2, l2); split_bf16(o3, h3, l3);
    uint2 hv; hv.x = pack2(h0, h1); hv.y = pack2(h2, h3);
    uint2 lv; lv.x = pack2(l0, l1); lv.y = pack2(l2, l3);
    *(uint2*)&o2[(size_t)row * 2048 + tid * 4]        = hv;
    *(uint2*)&o2[(size_t)row * 2048 + 1024 + tid * 4] = lv;
}

// ---------------- launch ----------------
extern "C" void kernel_launch(void* const* d_in, const int* in_sizes, int n_in,
                              void* d_out, int out_size)
{
    const float* x    = (const float*)d_in[0];
    const float* Wq   = (const float*)d_in[1];
    const float* bq   = (const float*)d_in[2];
    const float* Wk   = (const float*)d_in[3];
    const float* bk   = (const float*)d_in[4];
    const float* Wv   = (const float*)d_in[5];
    const float* bv   = (const float*)d_in[6];
    const float* Wu   = (const float*)d_in[7];
    const float* bu   = (const float*)d_in[8];
    const float* Wo   = (const float*)d_in[9];
    const float* bo   = (const float*)d_in[10];
    const float* ln_g = (const float*)d_in[11];
    const float* ln_b = (const float*)d_in[12];

    __nv_bfloat16 *x2, *w5, *g2, *q2, *k2, *v2;
    float *up, *ap;
    cudaGetSymbolAddress((void**)&x2, g_x2);
    cudaGetSymbolAddress((void**)&w5, g_w5);
    cudaGetSymbolAddress((void**)&g2, g_g2);
    cudaGetSymbolAddress((void**)&q2, g_q2);
    cudaGetSymbolAddress((void**)&k2, g_k2);
    cudaGetSymbolAddress((void**)&v2, g_v2);
    cudaGetSymbolAddress((void**)&up, g_u);
    cudaGetSymbolAddress((void**)&ap, g_attn);

    cudaFuncSetAttribute(proj_fused,
                         cudaFuncAttributeMaxDynamicSharedMemorySize, PROJ_SMEM);
    cudaFuncSetAttribute(proj_out,
                         cudaFuncAttributeMaxDynamicSharedMemorySize, PROJ_SMEM);
    cudaFuncSetAttribute(attn_mma2,
                         cudaFuncAttributeMaxDynamicSharedMemorySize, ATTN_SMEM);

    // splits: x (4096 rows) + all 5 weights in one batched launch
    split_kernel<<<4096, 256>>>(x, x2, 4096 * 1024 / 4);
    splitW_kernel<<<5120, 256>>>(Wq, Wk, Wv, Wu, Wo, w5);

    // fused Q/K/V/U projection
    proj_fused<<<dim3(32, 32), 256, PROJ_SMEM>>>(
        x2, w5, bq, bk, bv, bu, q2, k2, v2, up);

    attn_mma2<<<dim3(SEQ / 128, 32), 256, ATTN_SMEM>>>(q2, k2, v2, ap);

    ln_gate<<<MTOT, 256>>>(ap, up, ln_g, ln_b, g2);

    proj_out<<<dim3(8, 32), 256, PROJ_SMEM>>>(
        g2, w5 + (size_t)4096 * 2048, bo, (float*)d_out);
}

// round 8
// speedup vs baseline: 3.1116x; 1.0162x over previous
#include <cuda_runtime.h>
#include <cuda_bf16.h>
#include <stdint.h>
#include <math.h>

// Problem dims (fixed)
#define MTOT 4096   // B*N
#define ETOT 1024
#define SEQ  2048
#define NH   16
#define HDIM 64

// ---------------- scratch (device globals) ----------------
__device__ __nv_bfloat16 g_x2[4096 * 2048];        // x split  [4096][hi 1024 | lo 1024]
__device__ __nv_bfloat16 g_w5[5120 * 2048];        // W splits packed rows: q,k,v,u,o
__device__ __nv_bfloat16 g_g2[4096 * 2048];        // gate split [hi|lo]
__device__ __nv_bfloat16 g_q2[32 * 2048 * 128];    // [bh][n][hi 64 | lo 64]
__device__ __nv_bfloat16 g_k2[32 * 2048 * 128];
__device__ __nv_bfloat16 g_v2[32 * 2048 * 128];
__device__ float g_u[4096 * 1024];
__device__ float g_attn[4096 * 1024];

// ---------------- helpers ----------------
__device__ __forceinline__ unsigned smem_u32(const void* p) {
    return (unsigned)__cvta_generic_to_shared(p);
}
__device__ __forceinline__ void ldmat_x4(unsigned addr, unsigned* r) {
    asm volatile("ldmatrix.sync.aligned.m8n8.x4.shared.b16 {%0,%1,%2,%3}, [%4];\n"
                 : "=r"(r[0]), "=r"(r[1]), "=r"(r[2]), "=r"(r[3]) : "r"(addr));
}
__device__ __forceinline__ void ldmat_x4_t(unsigned addr, unsigned* r) {
    asm volatile("ldmatrix.sync.aligned.m8n8.x4.trans.shared.b16 {%0,%1,%2,%3}, [%4];\n"
                 : "=r"(r[0]), "=r"(r[1]), "=r"(r[2]), "=r"(r[3]) : "r"(addr));
}
__device__ __forceinline__ void mma_bf16(float* c, const unsigned* a, const unsigned* b) {
    asm volatile(
        "mma.sync.aligned.m16n8k16.row.col.f32.bf16.bf16.f32 "
        "{%0,%1,%2,%3}, {%4,%5,%6,%7}, {%8,%9}, {%0,%1,%2,%3};\n"
        : "+f"(c[0]), "+f"(c[1]), "+f"(c[2]), "+f"(c[3])
        : "r"(a[0]), "r"(a[1]), "r"(a[2]), "r"(a[3]), "r"(b[0]), "r"(b[1]));
}
__device__ __forceinline__ void split_bf16(float x, __nv_bfloat16& hi, __nv_bfloat16& lo) {
    hi = __float2bfloat16(x);
    lo = __float2bfloat16(x - __bfloat162float(hi));
}
__device__ __forceinline__ unsigned pack2(__nv_bfloat16 a, __nv_bfloat16 b) {
    __nv_bfloat162 t; t.x = a; t.y = b;
    return *(unsigned*)&t;
}
__device__ __forceinline__ void cp16(unsigned dst, const void* src) {
    asm volatile("cp.async.cg.shared.global [%0], [%1], 16;\n" :: "r"(dst), "l"(src));
}
__device__ __forceinline__ void cp_commit() { asm volatile("cp.async.commit_group;\n"); }
__device__ __forceinline__ void cp_wait0()  { asm volatile("cp.async.wait_group 0;\n" ::: "memory"); }
__device__ __forceinline__ void cp_wait1()  { asm volatile("cp.async.wait_group 1;\n" ::: "memory"); }

// ---------------- unified split: x + 5 weights, one launch ----------------
// blockIdx.x = row (0..9215): rows [0,4096) -> x -> outX; rows [4096,9216) -> W -> outW
__global__ __launch_bounds__(256) void split_all_kernel(
    const float* __restrict__ x,
    const float* __restrict__ w0, const float* __restrict__ w1,
    const float* __restrict__ w2, const float* __restrict__ w3,
    const float* __restrict__ w4,
    __nv_bfloat16* __restrict__ outX, __nv_bfloat16* __restrict__ outW)
{
    int row = blockIdx.x;
    int c = threadIdx.x << 2;
    const float* src;
    __nv_bfloat16* dst;
    if (row < 4096) {
        src = x + (size_t)row * 1024;
        dst = outX + (size_t)row * 2048;
    } else {
        int wrow = row - 4096;
        int which = wrow >> 10;
        int r = wrow & 1023;
        const float* w = (which == 0) ? w0 : (which == 1) ? w1 :
                         (which == 2) ? w2 : (which == 3) ? w3 : w4;
        src = w + (size_t)r * 1024;
        dst = outW + (size_t)wrow * 2048;
    }
    float4 a = *(const float4*)&src[c];
    __nv_bfloat16 h0, h1, h2, h3, l0, l1, l2, l3;
    split_bf16(a.x, h0, l0); split_bf16(a.y, h1, l1);
    split_bf16(a.z, h2, l2); split_bf16(a.w, h3, l3);
    uint2 hv; hv.x = pack2(h0, h1); hv.y = pack2(h2, h3);
    uint2 lv; lv.x = pack2(l0, l1); lv.y = pack2(l2, l3);
    *(uint2*)&dst[c] = hv;
    *(uint2*)&dst[1024 + c] = lv;
}

// ================= projection GEMM core (3-stage cp.async, 1 sync/chunk) =================
#define PPITCH 72
#define PSTG_ELEM (2 * 128 * PPITCH)          // bf16 elems per stage (A+B)
#define PROJ_SMEM (3 * PSTG_ELEM * 2)

__device__ __forceinline__ void proj_load_chunk(
    const __nv_bfloat16* __restrict__ A2, const __nv_bfloat16* __restrict__ B2,
    __nv_bfloat16* As, __nv_bfloat16* Bs, int mB, int nB, int kb, int tid)
{
#pragma unroll
    for (int t = 0; t < 4; t++) {
        int idx = tid + t * 256;            // 0..1023
        int row = idx >> 3, s = idx & 7;    // 8 x 16B slices per row
        int gcol = (s < 4) ? (kb + s * 8) : (1024 + kb + (s - 4) * 8);
        int scol = (s < 4) ? (s * 8) : (32 + (s - 4) * 8);
        cp16(smem_u32(&As[row * PPITCH + scol]), &A2[(size_t)(mB + row) * 2048 + gcol]);
        cp16(smem_u32(&Bs[row * PPITCH + scol]), &B2[(size_t)(nB + row) * 2048 + gcol]);
    }
}

__device__ __forceinline__ void proj_mainloop(
    const __nv_bfloat16* __restrict__ A2, const __nv_bfloat16* __restrict__ B2,
    __nv_bfloat16* smb, int mB, int nB, int tid, int lane,
    int warpM, int warpN, float acc[2][8][4])
{
#pragma unroll
    for (int mt = 0; mt < 2; mt++)
#pragma unroll
        for (int nt = 0; nt < 8; nt++)
#pragma unroll
            for (int r = 0; r < 4; r++) acc[mt][nt][r] = 0.f;

    __nv_bfloat16* stA[3] = { smb, smb + PSTG_ELEM, smb + 2 * PSTG_ELEM };
    proj_load_chunk(A2, B2, stA[0], stA[0] + 128 * PPITCH, mB, nB, 0, tid);
    cp_commit();
    proj_load_chunk(A2, B2, stA[1], stA[1] + 128 * PPITCH, mB, nB, 32, tid);
    cp_commit();

    for (int c = 0; c < 32; c++) {
        if (c < 31) cp_wait1(); else cp_wait0();
        __syncthreads();
        // issue c+2 AFTER the sync: the sync guarantees all warps finished
        // compute on stage (c+2)%3 == (c-1)%3 in iteration c-1.
        if (c + 2 < 32) {
            __nv_bfloat16* st = stA[(c + 2) % 3];
            proj_load_chunk(A2, B2, st, st + 128 * PPITCH, mB, nB, (c + 2) * 32, tid);
            cp_commit();
        }

        const __nv_bfloat16* As = stA[c % 3];
        const __nv_bfloat16* Bs = As + 128 * PPITCH;
#pragma unroll
        for (int ks = 0; ks < 2; ks++) {
            const int kk = ks * 16;
            unsigned ahi[2][4], alo[2][4];
#pragma unroll
            for (int mt = 0; mt < 2; mt++) {
                int arow = warpM * 32 + mt * 16 + (lane & 15);
                int ako = kk + ((lane >> 4) << 3);
                ldmat_x4(smem_u32(&As[arow * PPITCH + ako]), ahi[mt]);
                ldmat_x4(smem_u32(&As[arow * PPITCH + 32 + ako]), alo[mt]);
            }
#pragma unroll
            for (int p = 0; p < 4; p++) {
                unsigned bh_[4], bl_[4];
                int nrow = warpN * 64 + p * 16 + ((lane >> 4) << 3) + (lane & 7);
                int kc = kk + (((lane >> 3) & 1) << 3);
                ldmat_x4(smem_u32(&Bs[nrow * PPITCH + kc]), bh_);
                ldmat_x4(smem_u32(&Bs[nrow * PPITCH + 32 + kc]), bl_);
#pragma unroll
                for (int mt = 0; mt < 2; mt++) {
                    mma_bf16(acc[mt][2 * p],     ahi[mt], &bh_[0]);
                    mma_bf16(acc[mt][2 * p + 1], ahi[mt], &bh_[2]);
                }
#pragma unroll
                for (int mt = 0; mt < 2; mt++) {
                    mma_bf16(acc[mt][2 * p],     alo[mt], &bh_[0]);
                    mma_bf16(acc[mt][2 * p + 1], alo[mt], &bh_[2]);
                }
#pragma unroll
                for (int mt = 0; mt < 2; mt++) {
                    mma_bf16(acc[mt][2 * p],     ahi[mt], &bl_[0]);
                    mma_bf16(acc[mt][2 * p + 1], ahi[mt], &bl_[2]);
                }
            }
        }
    }
}

// ---- fused Q/K/V/U projection: grid (32,32) ----
__global__ __launch_bounds__(256) void proj_fused(
    const __nv_bfloat16* __restrict__ A2, const __nv_bfloat16* __restrict__ W2,
    const float* __restrict__ b0, const float* __restrict__ b1,
    const float* __restrict__ b2, const float* __restrict__ b3,
    __nv_bfloat16* __restrict__ outQ, __nv_bfloat16* __restrict__ outK,
    __nv_bfloat16* __restrict__ outV, float* __restrict__ outU)
{
    extern __shared__ __nv_bfloat16 smb[];
    const int tid = threadIdx.x;
    const int lane = tid & 31, warp = tid >> 5;
    const int warpM = warp >> 1, warpN = warp & 1;
    const int mB = blockIdx.y * 128, nB = blockIdx.x * 128;
    const int g = lane >> 2, tig = lane & 3;
    const int which = nB >> 10;

    float acc[2][8][4];
    proj_mainloop(A2, W2, smb, mB, nB, tid, lane, warpM, warpN, acc);

    const float* bp = (which == 0) ? b0 : (which == 1) ? b1 : (which == 2) ? b2 : b3;
    __nv_bfloat16* outH = (which == 0) ? outQ : (which == 1) ? outK : outV;
    const int act = (which >= 2);

#pragma unroll
    for (int mt = 0; mt < 2; mt++)
#pragma unroll
        for (int nt = 0; nt < 8; nt++)
#pragma unroll
            for (int rp = 0; rp < 2; rp++) {
                int m = mB + warpM * 32 + mt * 16 + g + rp * 8;
                int e0 = nB + warpN * 64 + nt * 8 + 2 * tig;
                int eq = e0 & 1023;
                float v0 = acc[mt][nt][rp * 2]     + __ldg(&bp[eq]);
                float v1 = acc[mt][nt][rp * 2 + 1] + __ldg(&bp[eq + 1]);
                if (act) {
                    v0 = v0 / (1.f + __expf(-v0));
                    v1 = v1 / (1.f + __expf(-v1));
                }
                if (which == 3) {
                    float2 fv; fv.x = v0; fv.y = v1;
                    *(float2*)&outU[(size_t)m * ETOT + eq] = fv;
                } else {
                    int b = m >> 11, n = m & (SEQ - 1);
                    int h = eq >> 6, d = eq & (HDIM - 1);
                    __nv_bfloat16 h0, h1, l0, l1;
                    split_bf16(v0, h0, l0);
                    split_bf16(v1, h1, l1);
                    size_t base = (((size_t)b * NH + h) * SEQ + n) * 128 + d;
                    *(unsigned*)&outH[base]      = pack2(h0, h1);
                    *(unsigned*)&outH[base + 64] = pack2(l0, l1);
                }
            }
}

// ---- output projection: grid (8,32) ----
__global__ __launch_bounds__(256) void proj_out(
    const __nv_bfloat16* __restrict__ A2, const __nv_bfloat16* __restrict__ W2,
    const float* __restrict__ bias, float* __restrict__ outF)
{
    extern __shared__ __nv_bfloat16 smb[];
    const int tid = threadIdx.x;
    const int lane = tid & 31, warp = tid >> 5;
    const int warpM = warp >> 1, warpN = warp & 1;
    const int mB = blockIdx.y * 128, nB = blockIdx.x * 128;
    const int g = lane >> 2, tig = lane & 3;

    float acc[2][8][4];
    proj_mainloop(A2, W2, smb, mB, nB, tid, lane, warpM, warpN, acc);

#pragma unroll
    for (int mt = 0; mt < 2; mt++)
#pragma unroll
        for (int nt = 0; nt < 8; nt++)
#pragma unroll
            for (int rp = 0; rp < 2; rp++) {
                int m = mB + warpM * 32 + mt * 16 + g + rp * 8;
                int e0 = nB + warpN * 64 + nt * 8 + 2 * tig;
                float2 fv;
                fv.x = acc[mt][nt][rp * 2]     + __ldg(&bias[e0]);
                fv.y = acc[mt][nt][rp * 2 + 1] + __ldg(&bias[e0 + 1]);
                *(float2*)&outF[(size_t)m * ETOT + e0] = fv;
            }
}

// ================= attention: S-in-registers, double-buffered K/V =================
// Warp w owns q-rows [w*16, w*16+16), full 64 keys, full d=64.
// C-fragment of S (m16n8) feeds directly as A-fragment of S·V (m16n8k16).
#define QPITCH 136
#define VPITCH 72
#define KS_ELEM (64 * QPITCH)
#define VS_ELEM (128 * VPITCH)
#define ATTN_SMEM ((128 * QPITCH + 2 * KS_ELEM + 2 * VS_ELEM) * 2)

__device__ __forceinline__ void attn_load_kv(
    const __nv_bfloat16* kp, const __nv_bfloat16* vp,
    __nv_bfloat16* Ks, __nv_bfloat16* Vs, int kt, int tid)
{
#pragma unroll
    for (int t = 0; t < 4; t++) {
        int idx = tid + t * 256;
        int row = idx >> 4, s = idx & 15;
        cp16(smem_u32(&Ks[row * QPITCH + s * 8]), &kp[(size_t)(kt + row) * 128 + s * 8]);
        if (s < 8)
            cp16(smem_u32(&Vs[row * VPITCH + s * 8]), &vp[(size_t)(kt + row) * 128 + s * 8]);
        else
            cp16(smem_u32(&Vs[(64 + row) * VPITCH + (s - 8) * 8]),
                 &vp[(size_t)(kt + row) * 128 + s * 8]);
    }
}

__global__ __launch_bounds__(256, 2) void attn_mma3(
    const __nv_bfloat16* __restrict__ q2, const __nv_bfloat16* __restrict__ k2,
    const __nv_bfloat16* __restrict__ v2, float* __restrict__ attn)
{
    extern __shared__ __nv_bfloat16 smb[];
    __nv_bfloat16* Qs  = smb;                       // [128][136]
    __nv_bfloat16* Ks0 = Qs + 128 * QPITCH;         // [2][64][136]
    __nv_bfloat16* Vs0 = Ks0 + 2 * KS_ELEM;         // [2][128][72]

    const int tid = threadIdx.x;
    const int lane = tid & 31, warp = tid >> 5;     // warp 0..7 = m16 strip
    const int g = lane >> 2, tig = lane & 3;
    const int sel = lane >> 3, l8 = lane & 7;
    const int bh = blockIdx.y;
    const int qBase = blockIdx.x * 128;
    const __nv_bfloat16* qp = q2 + (size_t)bh * SEQ * 128;
    const __nv_bfloat16* kp = k2 + (size_t)bh * SEQ * 128;
    const __nv_bfloat16* vp = v2 + (size_t)bh * SEQ * 128;

    // Q (persistent)
#pragma unroll
    for (int t = 0; t < 8; t++) {
        int idx = tid + t * 256;
        int row = idx >> 4, s = idx & 15;
        cp16(smem_u32(&Qs[row * QPITCH + s * 8]), &qp[(size_t)(qBase + row) * 128 + s * 8]);
    }
    cp_commit();
    // KV tile 0 into buf 0
    attn_load_kv(kp, vp, Ks0, Vs0, 0, tid);
    cp_commit();

    float oacc[8][4];
#pragma unroll
    for (int nt = 0; nt < 8; nt++)
#pragma unroll
        for (int r = 0; r < 4; r++) oacc[nt][r] = 0.f;

    for (int tile = 0; tile < 32; tile++) {
        const int buf = tile & 1;
        cp_wait0();        // Q (tile 0) + KV(tile) complete; KV(tile+1) not yet issued
        __syncthreads();   // visibility + all warps finished reading buf^1 (tile-1)
        if (tile + 1 < 32) {
            attn_load_kv(kp, vp, Ks0 + (buf ^ 1) * KS_ELEM, Vs0 + (buf ^ 1) * VS_ELEM,
                         (tile + 1) * 64, tid);
            cp_commit();   // overlaps this tile's compute
        }
        const __nv_bfloat16* Ks = Ks0 + buf * KS_ELEM;
        const __nv_bfloat16* Vs = Vs0 + buf * VS_ELEM;

        // ---- phase 2: S[m16][64] = Q K^T (3-term) ----
        float sacc[8][4];
#pragma unroll
        for (int nt = 0; nt < 8; nt++)
#pragma unroll
            for (int r = 0; r < 4; r++) sacc[nt][r] = 0.f;

#pragma unroll
        for (int ks = 0; ks < 4; ks++) {
            const int kk = ks * 16;
            unsigned qhi[4], qlo[4];
            int arow = warp * 16 + (lane & 15);
            int ako = kk + ((lane >> 4) << 3);
            ldmat_x4(smem_u32(&Qs[arow * QPITCH + ako]), qhi);
            ldmat_x4(smem_u32(&Qs[arow * QPITCH + 64 + ako]), qlo);
#pragma unroll
            for (int p = 0; p < 4; p++) {
                unsigned kh_[4], kl_[4];
                int jrow = p * 16 + ((lane >> 4) << 3) + (lane & 7);
                int kc = kk + (((lane >> 3) & 1) << 3);
                ldmat_x4(smem_u32(&Ks[jrow * QPITCH + kc]), kh_);
                ldmat_x4(smem_u32(&Ks[jrow * QPITCH + 64 + kc]), kl_);
                mma_bf16(sacc[2 * p],     qhi, &kh_[0]);
                mma_bf16(sacc[2 * p + 1], qhi, &kh_[2]);
                mma_bf16(sacc[2 * p],     qlo, &kh_[0]);
                mma_bf16(sacc[2 * p + 1], qlo, &kh_[2]);
                mma_bf16(sacc[2 * p],     qhi, &kl_[0]);
                mma_bf16(sacc[2 * p + 1], qhi, &kl_[2]);
            }
        }

        // ---- phase 3: O += S V, S converted in registers per k16-chunk ----
#pragma unroll
        for (int t = 0; t < 4; t++) {
            unsigned ah[4], al[4];
#pragma unroll
            for (int j = 0; j < 2; j++) {
                float* s = sacc[2 * t + j];
                float s0 = s[0] * 0.125f, s1 = s[1] * 0.125f;
                float s2 = s[2] * 0.125f, s3 = s[3] * 0.125f;
                s0 = s0 > 0.f ? s0 : 0.f;  s1 = s1 > 0.f ? s1 : 0.f;
                s2 = s2 > 0.f ? s2 : 0.f;  s3 = s3 > 0.f ? s3 : 0.f;
                __nv_bfloat16 h0, h1, h2, h3, l0, l1, l2, l3;
                split_bf16(s0, h0, l0); split_bf16(s1, h1, l1);
                split_bf16(s2, h2, l2); split_bf16(s3, h3, l3);
                // C-frag (c0,c1 row g; c2,c3 row g+8) -> A-frag regs 2j, 2j+1
                ah[2 * j]     = pack2(h0, h1);
                ah[2 * j + 1] = pack2(h2, h3);
                al[2 * j]     = pack2(l0, l1);
                al[2 * j + 1] = pack2(l2, l3);
            }
#pragma unroll
            for (int p = 0; p < 4; p++) {
                unsigned vh_[4], vl_[4];
                int krh = t * 16 + ((sel & 1) << 3) + l8;
                int nc = p * 16 + ((sel >> 1) << 3);
                ldmat_x4_t(smem_u32(&Vs[krh * VPITCH + nc]), vh_);
                ldmat_x4_t(smem_u32(&Vs[(64 + krh) * VPITCH + nc]), vl_);
                mma_bf16(oacc[2 * p],     ah, &vh_[0]);
                mma_bf16(oacc[2 * p + 1], ah, &vh_[2]);
                mma_bf16(oacc[2 * p],     al, &vh_[0]);
                mma_bf16(oacc[2 * p + 1], al, &vh_[2]);
                mma_bf16(oacc[2 * p],     ah, &vl_[0]);
                mma_bf16(oacc[2 * p + 1], ah, &vl_[2]);
            }
        }
    }

    // store O: warp's m16 strip x d64
    const int b = bh >> 4, h = bh & 15;
#pragma unroll
    for (int nt = 0; nt < 8; nt++)
#pragma unroll
        for (int rp = 0; rp < 2; rp++) {
            int row = qBase + warp * 16 + g + rp * 8;
            int d0 = nt * 8 + 2 * tig;
            float2 fv;
            fv.x = oacc[nt][rp * 2];
            fv.y = oacc[nt][rp * 2 + 1];
            *(float2*)&attn[((size_t)b * SEQ + row) * ETOT + h * HDIM + d0] = fv;
        }
}

// ---------------- layernorm + gate; writes split bf16 gate ----------------
__global__ __launch_bounds__(256) void ln_gate(
    const float* __restrict__ a, const float* __restrict__ u,
    const float* __restrict__ gamma, const float* __restrict__ beta,
    __nv_bfloat16* __restrict__ o2)
{
    const int row = blockIdx.x;
    const int tid = threadIdx.x;
    const float* ar = a + (size_t)row * ETOT;
    float4 xv = *(const float4*)&ar[tid * 4];

    float s1 = xv.x + xv.y + xv.z + xv.w;
    float s2 = xv.x * xv.x + xv.y * xv.y + xv.z * xv.z + xv.w * xv.w;
#pragma unroll
    for (int o = 16; o > 0; o >>= 1) {
        s1 += __shfl_xor_sync(0xffffffffu, s1, o);
        s2 += __shfl_xor_sync(0xffffffffu, s2, o);
    }
    __shared__ float r1[8], r2[8];
    __shared__ float mu_s, inv_s;
    if ((tid & 31) == 0) { r1[tid >> 5] = s1; r2[tid >> 5] = s2; }
    __syncthreads();
    if (tid == 0) {
        float t1 = 0.f, t2 = 0.f;
#pragma unroll
        for (int i = 0; i < 8; i++) { t1 += r1[i]; t2 += r2[i]; }
        float mu = t1 * (1.f / ETOT);
        float var = t2 * (1.f / ETOT) - mu * mu;
        mu_s = mu;
        inv_s = rsqrtf(var + 1e-5f);
    }
    __syncthreads();
    const float mu = mu_s, inv = inv_s;

    float4 gv = *(const float4*)&gamma[tid * 4];
    float4 bv = *(const float4*)&beta[tid * 4];
    float4 uv = *(const float4*)&u[(size_t)row * ETOT + tid * 4];
    float o0 = ((xv.x - mu) * inv * gv.x + bv.x) * uv.x;
    float o1 = ((xv.y - mu) * inv * gv.y + bv.y) * uv.y;
    float o2v = ((xv.z - mu) * inv * gv.z + bv.z) * uv.z;
    float o3 = ((xv.w - mu) * inv * gv.w + bv.w) * uv.w;
    __nv_bfloat16 h0, h1, h2, h3, l0, l1, l2, l3;
    split_bf16(o0, h0, l0); split_bf16(o1, h1, l1);
    split_bf16(o2v, h2, l2); split_bf16(o3, h3, l3);
    uint2 hv; hv.x = pack2(h0, h1); hv.y = pack2(h2, h3);
    uint2 lv; lv.x = pack2(l0, l1); lv.y = pack2(l2, l3);
    *(uint2*)&o2[(size_t)row * 2048 + tid * 4]        = hv;
    *(uint2*)&o2[(size_t)row * 2048 + 1024 + tid * 4] = lv;
}

// ---------------- launch ----------------
extern "C" void kernel_launch(void* const* d_in, const int* in_sizes, int n_in,
                              void* d_out, int out_size)
{
    const float* x    = (const float*)d_in[0];
    const float* Wq   = (const float*)d_in[1];
    const float* bq   = (const float*)d_in[2];
    const float* Wk   = (const float*)d_in[3];
    const float* bk   = (const float*)d_in[4];
    const float* Wv   = (const float*)d_in[5];
    const float* bv   = (const float*)d_in[6];
    const float* Wu   = (const float*)d_in[7];
    const float* bu   = (const float*)d_in[8];
    const float* Wo   = (const float*)d_in[9];
    const float* bo   = (const float*)d_in[10];
    const float* ln_g = (const float*)d_in[11];
    const float* ln_b = (const float*)d_in[12];

    __nv_bfloat16 *x2, *w5, *g2, *q2, *k2, *v2;
    float *up, *ap;
    cudaGetSymbolAddress((void**)&x2, g_x2);
    cudaGetSymbolAddress((void**)&w5, g_w5);
    cudaGetSymbolAddress((void**)&g2, g_g2);
    cudaGetSymbolAddress((void**)&q2, g_q2);
    cudaGetSymbolAddress((void**)&k2, g_k2);
    cudaGetSymbolAddress((void**)&v2, g_v2);
    cudaGetSymbolAddress((void**)&up, g_u);
    cudaGetSymbolAddress((void**)&ap, g_attn);

    cudaFuncSetAttribute(proj_fused,
                         cudaFuncAttributeMaxDynamicSharedMemorySize, PROJ_SMEM);
    cudaFuncSetAttribute(proj_out,
                         cudaFuncAttributeMaxDynamicSharedMemorySize, PROJ_SMEM);
    cudaFuncSetAttribute(attn_mma3,
                         cudaFuncAttributeMaxDynamicSharedMemorySize, ATTN_SMEM);

    split_all_kernel<<<9216, 256>>>(x, Wq, Wk, Wv, Wu, Wo, x2, w5);

    proj_fused<<<dim3(32, 32), 256, PROJ_SMEM>>>(
        x2, w5, bq, bk, bv, bu, q2, k2, v2, up);

    attn_mma3<<<dim3(SEQ / 128, 32), 256, ATTN_SMEM>>>(q2, k2, v2, ap);

    ln_gate<<<MTOT, 256>>>(ap, up, ln_g, ln_b, g2);

    proj_out<<<dim3(8, 32), 256, PROJ_SMEM>>>(
        g2, w5 + (size_t)4096 * 2048, bo, (float*)d_out);
}

// round 9
// speedup vs baseline: 3.1124x; 1.0003x over previous
#include <cuda_runtime.h>
#include <cuda_bf16.h>
#include <stdint.h>
#include <math.h>

// Problem dims (fixed)
#define MTOT 4096   // B*N
#define ETOT 1024
#define SEQ  2048
#define NH   16
#define HDIM 64

// ---------------- scratch (device globals) ----------------
__device__ __nv_bfloat16 g_x2[4096 * 2048];        // x split  [4096][hi 1024 | lo 1024]
__device__ __nv_bfloat16 g_w5[5120 * 2048];        // W splits packed rows: q,k,v,u,o
__device__ __nv_bfloat16 g_g2[4096 * 2048];        // gate split [hi|lo]
__device__ __nv_bfloat16 g_q2[32 * 2048 * 128];    // [bh][n][hi 64 | lo 64]
__device__ __nv_bfloat16 g_k2[32 * 2048 * 128];
__device__ __nv_bfloat16 g_v2[32 * 2048 * 128];
__device__ float g_u[4096 * 1024];
__device__ float g_attn[4096 * 1024];

// ---------------- helpers ----------------
__device__ __forceinline__ unsigned smem_u32(const void* p) {
    return (unsigned)__cvta_generic_to_shared(p);
}
__device__ __forceinline__ void ldmat_x4(unsigned addr, unsigned* r) {
    asm volatile("ldmatrix.sync.aligned.m8n8.x4.shared.b16 {%0,%1,%2,%3}, [%4];\n"
                 : "=r"(r[0]), "=r"(r[1]), "=r"(r[2]), "=r"(r[3]) : "r"(addr));
}
__device__ __forceinline__ void ldmat_x4_t(unsigned addr, unsigned* r) {
    asm volatile("ldmatrix.sync.aligned.m8n8.x4.trans.shared.b16 {%0,%1,%2,%3}, [%4];\n"
                 : "=r"(r[0]), "=r"(r[1]), "=r"(r[2]), "=r"(r[3]) : "r"(addr));
}
__device__ __forceinline__ void mma_bf16(float* c, const unsigned* a, const unsigned* b) {
    asm volatile(
        "mma.sync.aligned.m16n8k16.row.col.f32.bf16.bf16.f32 "
        "{%0,%1,%2,%3}, {%4,%5,%6,%7}, {%8,%9}, {%0,%1,%2,%3};\n"
        : "+f"(c[0]), "+f"(c[1]), "+f"(c[2]), "+f"(c[3])
        : "r"(a[0]), "r"(a[1]), "r"(a[2]), "r"(a[3]), "r"(b[0]), "r"(b[1]));
}
__device__ __forceinline__ void split_bf16(float x, __nv_bfloat16& hi, __nv_bfloat16& lo) {
    hi = __float2bfloat16(x);
    lo = __float2bfloat16(x - __bfloat162float(hi));
}
__device__ __forceinline__ unsigned pack2(__nv_bfloat16 a, __nv_bfloat16 b) {
    __nv_bfloat162 t; t.x = a; t.y = b;
    return *(unsigned*)&t;
}
__device__ __forceinline__ void cp16(unsigned dst, const void* src) {
    asm volatile("cp.async.cg.shared.global [%0], [%1], 16;\n" :: "r"(dst), "l"(src));
}
__device__ __forceinline__ void cp_commit() { asm volatile("cp.async.commit_group;\n"); }
__device__ __forceinline__ void cp_wait0()  { asm volatile("cp.async.wait_group 0;\n" ::: "memory"); }
__device__ __forceinline__ void cp_wait1()  { asm volatile("cp.async.wait_group 1;\n" ::: "memory"); }

// ---------------- unified split: x + 5 weights, one launch ----------------
// blockIdx.x = row (0..9215): rows [0,4096) -> x -> outX; rows [4096,9216) -> W -> outW
__global__ __launch_bounds__(256) void split_all_kernel(
    const float* __restrict__ x,
    const float* __restrict__ w0, const float* __restrict__ w1,
    const float* __restrict__ w2, const float* __restrict__ w3,
    const float* __restrict__ w4,
    __nv_bfloat16* __restrict__ outX, __nv_bfloat16* __restrict__ outW)
{
    int row = blockIdx.x;
    int c = threadIdx.x << 2;
    const float* src;
    __nv_bfloat16* dst;
    if (row < 4096) {
        src = x + (size_t)row * 1024;
        dst = outX + (size_t)row * 2048;
    } else {
        int wrow = row - 4096;
        int which = wrow >> 10;
        int r = wrow & 1023;
        const float* w = (which == 0) ? w0 : (which == 1) ? w1 :
                         (which == 2) ? w2 : (which == 3) ? w3 : w4;
        src = w + (size_t)r * 1024;
        dst = outW + (size_t)wrow * 2048;
    }
    float4 a = *(const float4*)&src[c];
    __nv_bfloat16 h0, h1, h2, h3, l0, l1, l2, l3;
    split_bf16(a.x, h0, l0); split_bf16(a.y, h1, l1);
    split_bf16(a.z, h2, l2); split_bf16(a.w, h3, l3);
    uint2 hv; hv.x = pack2(h0, h1); hv.y = pack2(h2, h3);
    uint2 lv; lv.x = pack2(l0, l1); lv.y = pack2(l2, l3);
    *(uint2*)&dst[c] = hv;
    *(uint2*)&dst[1024 + c] = lv;
}

// ================= projection GEMM core (3-stage cp.async, 1 sync/chunk) =================
#define PPITCH 72
#define PSTG_ELEM (2 * 128 * PPITCH)          // bf16 elems per stage (A+B)
#define PROJ_SMEM (3 * PSTG_ELEM * 2)

__device__ __forceinline__ void proj_load_chunk(
    const __nv_bfloat16* __restrict__ A2, const __nv_bfloat16* __restrict__ B2,
    __nv_bfloat16* As, __nv_bfloat16* Bs, int mB, int nB, int kb, int tid)
{
#pragma unroll
    for (int t = 0; t < 4; t++) {
        int idx = tid + t * 256;            // 0..1023
        int row = idx >> 3, s = idx & 7;    // 8 x 16B slices per row
        int gcol = (s < 4) ? (kb + s * 8) : (1024 + kb + (s - 4) * 8);
        int scol = (s < 4) ? (s * 8) : (32 + (s - 4) * 8);
        cp16(smem_u32(&As[row * PPITCH + scol]), &A2[(size_t)(mB + row) * 2048 + gcol]);
        cp16(smem_u32(&Bs[row * PPITCH + scol]), &B2[(size_t)(nB + row) * 2048 + gcol]);
    }
}

__device__ __forceinline__ void proj_mainloop(
    const __nv_bfloat16* __restrict__ A2, const __nv_bfloat16* __restrict__ B2,
    __nv_bfloat16* smb, int mB, int nB, int tid, int lane,
    int warpM, int warpN, float acc[2][8][4])
{
#pragma unroll
    for (int mt = 0; mt < 2; mt++)
#pragma unroll
        for (int nt = 0; nt < 8; nt++)
#pragma unroll
            for (int r = 0; r < 4; r++) acc[mt][nt][r] = 0.f;

    __nv_bfloat16* stA[3] = { smb, smb + PSTG_ELEM, smb + 2 * PSTG_ELEM };
    proj_load_chunk(A2, B2, stA[0], stA[0] + 128 * PPITCH, mB, nB, 0, tid);
    cp_commit();
    proj_load_chunk(A2, B2, stA[1], stA[1] + 128 * PPITCH, mB, nB, 32, tid);
    cp_commit();

    for (int c = 0; c < 32; c++) {
        if (c < 31) cp_wait1(); else cp_wait0();
        __syncthreads();
        // issue c+2 AFTER the sync: the sync guarantees all warps finished
        // compute on stage (c+2)%3 == (c-1)%3 in iteration c-1.
        if (c + 2 < 32) {
            __nv_bfloat16* st = stA[(c + 2) % 3];
            proj_load_chunk(A2, B2, st, st + 128 * PPITCH, mB, nB, (c + 2) * 32, tid);
            cp_commit();
        }

        const __nv_bfloat16* As = stA[c % 3];
        const __nv_bfloat16* Bs = As + 128 * PPITCH;
#pragma unroll
        for (int ks = 0; ks < 2; ks++) {
            const int kk = ks * 16;
            unsigned ahi[2][4], alo[2][4];
#pragma unroll
            for (int mt = 0; mt < 2; mt++) {
                int arow = warpM * 32 + mt * 16 + (lane & 15);
                int ako = kk + ((lane >> 4) << 3);
                ldmat_x4(smem_u32(&As[arow * PPITCH + ako]), ahi[mt]);
                ldmat_x4(smem_u32(&As[arow * PPITCH + 32 + ako]), alo[mt]);
            }
#pragma unroll
            for (int p = 0; p < 4; p++) {
                unsigned bh_[4], bl_[4];
                int nrow = warpN * 64 + p * 16 + ((lane >> 4) << 3) + (lane & 7);
                int kc = kk + (((lane >> 3) & 1) << 3);
                ldmat_x4(smem_u32(&Bs[nrow * PPITCH + kc]), bh_);
                ldmat_x4(smem_u32(&Bs[nrow * PPITCH + 32 + kc]), bl_);
#pragma unroll
                for (int mt = 0; mt < 2; mt++) {
                    mma_bf16(acc[mt][2 * p],     ahi[mt], &bh_[0]);
                    mma_bf16(acc[mt][2 * p + 1], ahi[mt], &bh_[2]);
                }
#pragma unroll
                for (int mt = 0; mt < 2; mt++) {
                    mma_bf16(acc[mt][2 * p],     alo[mt], &bh_[0]);
                    mma_bf16(acc[mt][2 * p + 1], alo[mt], &bh_[2]);
                }
#pragma unroll
                for (int mt = 0; mt < 2; mt++) {
                    mma_bf16(acc[mt][2 * p],     ahi[mt], &bl_[0]);
                    mma_bf16(acc[mt][2 * p + 1], ahi[mt], &bl_[2]);
                }
            }
        }
    }
}

// ---- fused Q/K/V/U projection: grid (32,32) ----
__global__ __launch_bounds__(256) void proj_fused(
    const __nv_bfloat16* __restrict__ A2, const __nv_bfloat16* __restrict__ W2,
    const float* __restrict__ b0, const float* __restrict__ b1,
    const float* __restrict__ b2, const float* __restrict__ b3,
    __nv_bfloat16* __restrict__ outQ, __nv_bfloat16* __restrict__ outK,
    __nv_bfloat16* __restrict__ outV, float* __restrict__ outU)
{
    extern __shared__ __nv_bfloat16 smb[];
    const int tid = threadIdx.x;
    const int lane = tid & 31, warp = tid >> 5;
    const int warpM = warp >> 1, warpN = warp & 1;
    const int mB = blockIdx.y * 128, nB = blockIdx.x * 128;
    const int g = lane >> 2, tig = lane & 3;
    const int which = nB >> 10;

    float acc[2][8][4];
    proj_mainloop(A2, W2, smb, mB, nB, tid, lane, warpM, warpN, acc);

    const float* bp = (which == 0) ? b0 : (which == 1) ? b1 : (which == 2) ? b2 : b3;
    __nv_bfloat16* outH = (which == 0) ? outQ : (which == 1) ? outK : outV;
    const int act = (which >= 2);

#pragma unroll
    for (int mt = 0; mt < 2; mt++)
#pragma unroll
        for (int nt = 0; nt < 8; nt++)
#pragma unroll
            for (int rp = 0; rp < 2; rp++) {
                int m = mB + warpM * 32 + mt * 16 + g + rp * 8;
                int e0 = nB + warpN * 64 + nt * 8 + 2 * tig;
                int eq = e0 & 1023;
                float v0 = acc[mt][nt][rp * 2]     + __ldg(&bp[eq]);
                float v1 = acc[mt][nt][rp * 2 + 1] + __ldg(&bp[eq + 1]);
                if (act) {
                    v0 = v0 / (1.f + __expf(-v0));
                    v1 = v1 / (1.f + __expf(-v1));
                }
                if (which == 3) {
                    float2 fv; fv.x = v0; fv.y = v1;
                    *(float2*)&outU[(size_t)m * ETOT + eq] = fv;
                } else {
                    int b = m >> 11, n = m & (SEQ - 1);
                    int h = eq >> 6, d = eq & (HDIM - 1);
                    __nv_bfloat16 h0, h1, l0, l1;
                    split_bf16(v0, h0, l0);
                    split_bf16(v1, h1, l1);
                    size_t base = (((size_t)b * NH + h) * SEQ + n) * 128 + d;
                    *(unsigned*)&outH[base]      = pack2(h0, h1);
                    *(unsigned*)&outH[base + 64] = pack2(l0, l1);
                }
            }
}

// ---- output projection: grid (8,32) ----
__global__ __launch_bounds__(256) void proj_out(
    const __nv_bfloat16* __restrict__ A2, const __nv_bfloat16* __restrict__ W2,
    const float* __restrict__ bias, float* __restrict__ outF)
{
    extern __shared__ __nv_bfloat16 smb[];
    const int tid = threadIdx.x;
    const int lane = tid & 31, warp = tid >> 5;
    const int warpM = warp >> 1, warpN = warp & 1;
    const int mB = blockIdx.y * 128, nB = blockIdx.x * 128;
    const int g = lane >> 2, tig = lane & 3;

    float acc[2][8][4];
    proj_mainloop(A2, W2, smb, mB, nB, tid, lane, warpM, warpN, acc);

#pragma unroll
    for (int mt = 0; mt < 2; mt++)
#pragma unroll
        for (int nt = 0; nt < 8; nt++)
#pragma unroll
            for (int rp = 0; rp < 2; rp++) {
                int m = mB + warpM * 32 + mt * 16 + g + rp * 8;
                int e0 = nB + warpN * 64 + nt * 8 + 2 * tig;
                float2 fv;
                fv.x = acc[mt][nt][rp * 2]     + __ldg(&bias[e0]);
                fv.y = acc[mt][nt][rp * 2 + 1] + __ldg(&bias[e0 + 1]);
                *(float2*)&outF[(size_t)m * ETOT + e0] = fv;
            }
}

// ================= attention: S-in-registers, double-buffered K/V =================
// Warp w owns q-rows [w*16, w*16+16), full 64 keys, full d=64.
// C-fragment of S (m16n8) feeds directly as A-fragment of S·V (m16n8k16).
#define QPITCH 136
#define VPITCH 72
#define KS_ELEM (64 * QPITCH)
#define VS_ELEM (128 * VPITCH)
#define ATTN_SMEM ((128 * QPITCH + 2 * KS_ELEM + 2 * VS_ELEM) * 2)

__device__ __forceinline__ void attn_load_kv(
    const __nv_bfloat16* kp, const __nv_bfloat16* vp,
    __nv_bfloat16* Ks, __nv_bfloat16* Vs, int kt, int tid)
{
#pragma unroll
    for (int t = 0; t < 4; t++) {
        int idx = tid + t * 256;
        int row = idx >> 4, s = idx & 15;
        cp16(smem_u32(&Ks[row * QPITCH + s * 8]), &kp[(size_t)(kt + row) * 128 + s * 8]);
        if (s < 8)
            cp16(smem_u32(&Vs[row * VPITCH + s * 8]), &vp[(size_t)(kt + row) * 128 + s * 8]);
        else
            cp16(smem_u32(&Vs[(64 + row) * VPITCH + (s - 8) * 8]),
                 &vp[(size_t)(kt + row) * 128 + s * 8]);
    }
}

__global__ __launch_bounds__(256, 2) void attn_mma3(
    const __nv_bfloat16* __restrict__ q2, const __nv_bfloat16* __restrict__ k2,
    const __nv_bfloat16* __restrict__ v2, float* __restrict__ attn)
{
    extern __shared__ __nv_bfloat16 smb[];
    __nv_bfloat16* Qs  = smb;                       // [128][136]
    __nv_bfloat16* Ks0 = Qs + 128 * QPITCH;         // [2][64][136]
    __nv_bfloat16* Vs0 = Ks0 + 2 * KS_ELEM;         // [2][128][72]

    const int tid = threadIdx.x;
    const int lane = tid & 31, warp = tid >> 5;     // warp 0..7 = m16 strip
    const int g = lane >> 2, tig = lane & 3;
    const int sel = lane >> 3, l8 = lane & 7;
    const int bh = blockIdx.y;
    const int qBase = blockIdx.x * 128;
    const __nv_bfloat16* qp = q2 + (size_t)bh * SEQ * 128;
    const __nv_bfloat16* kp = k2 + (size_t)bh * SEQ * 128;
    const __nv_bfloat16* vp = v2 + (size_t)bh * SEQ * 128;

    // Q (persistent)
#pragma unroll
    for (int t = 0; t < 8; t++) {
        int idx = tid + t * 256;
        int row = idx >> 4, s = idx & 15;
        cp16(smem_u32(&Qs[row * QPITCH + s * 8]), &qp[(size_t)(qBase + row) * 128 + s * 8]);
    }
    cp_commit();
    // KV tile 0 into buf 0
    attn_load_kv(kp, vp, Ks0, Vs0, 0, tid);
    cp_commit();

    float oacc[8][4];
#pragma unroll
    for (int nt = 0; nt < 8; nt++)
#pragma unroll
        for (int r = 0; r < 4; r++) oacc[nt][r] = 0.f;

    for (int tile = 0; tile < 32; tile++) {
        const int buf = tile & 1;
        cp_wait0();        // Q (tile 0) + KV(tile) complete; KV(tile+1) not yet issued
        __syncthreads();   // visibility + all warps finished reading buf^1 (tile-1)
        if (tile + 1 < 32) {
            attn_load_kv(kp, vp, Ks0 + (buf ^ 1) * KS_ELEM, Vs0 + (buf ^ 1) * VS_ELEM,
                         (tile + 1) * 64, tid);
            cp_commit();   // overlaps this tile's compute
        }
        const __nv_bfloat16* Ks = Ks0 + buf * KS_ELEM;
        const __nv_bfloat16* Vs = Vs0 + buf * VS_ELEM;

        // ---- phase 2: S[m16][64] = Q K^T (3-term) ----
        float sacc[8][4];
#pragma unroll
        for (int nt = 0; nt < 8; nt++)
#pragma unroll
            for (int r = 0; r < 4; r++) sacc[nt][r] = 0.f;

#pragma unroll
        for (int ks = 0; ks < 4; ks++) {
            const int kk = ks * 16;
            unsigned qhi[4], qlo[4];
            int arow = warp * 16 + (lane & 15);
            int ako = kk + ((lane >> 4) << 3);
            ldmat_x4(smem_u32(&Qs[arow * QPITCH + ako]), qhi);
            ldmat_x4(smem_u32(&Qs[arow * QPITCH + 64 + ako]), qlo);
#pragma unroll
            for (int p = 0; p < 4; p++) {
                unsigned kh_[4], kl_[4];
                int jrow = p * 16 + ((lane >> 4) << 3) + (lane & 7);
                int kc = kk + (((lane >> 3) & 1) << 3);
                ldmat_x4(smem_u32(&Ks[jrow * QPITCH + kc]), kh_);
                ldmat_x4(smem_u32(&Ks[jrow * QPITCH + 64 + kc]), kl_);
                mma_bf16(sacc[2 * p],     qhi, &kh_[0]);
                mma_bf16(sacc[2 * p + 1], qhi, &kh_[2]);
                mma_bf16(sacc[2 * p],     qlo, &kh_[0]);
                mma_bf16(sacc[2 * p + 1], qlo, &kh_[2]);
                mma_bf16(sacc[2 * p],     qhi, &kl_[0]);
                mma_bf16(sacc[2 * p + 1], qhi, &kl_[2]);
            }
        }

        // ---- phase 3: O += S V, S converted in registers per k16-chunk ----
#pragma unroll
        for (int t = 0; t < 4; t++) {
            unsigned ah[4], al[4];
#pragma unroll
            for (int j = 0; j < 2; j++) {
                float* s = sacc[2 * t + j];
                float s0 = s[0] * 0.125f, s1 = s[1] * 0.125f;
                float s2 = s[2] * 0.125f, s3 = s[3] * 0.125f;
                s0 = s0 > 0.f ? s0 : 0.f;  s1 = s1 > 0.f ? s1 : 0.f;
                s2 = s2 > 0.f ? s2 : 0.f;  s3 = s3 > 0.f ? s3 : 0.f;
                __nv_bfloat16 h0, h1, h2, h3, l0, l1, l2, l3;
                split_bf16(s0, h0, l0); split_bf16(s1, h1, l1);
                split_bf16(s2, h2, l2); split_bf16(s3, h3, l3);
                // C-frag (c0,c1 row g; c2,c3 row g+8) -> A-frag regs 2j, 2j+1
                ah[2 * j]     = pack2(h0, h1);
                ah[2 * j + 1] = pack2(h2, h3);
                al[2 * j]     = pack2(l0, l1);
                al[2 * j + 1] = pack2(l2, l3);
            }
#pragma unroll
            for (int p = 0; p < 4; p++) {
                unsigned vh_[4], vl_[4];
                int krh = t * 16 + ((sel & 1) << 3) + l8;
                int nc = p * 16 + ((sel >> 1) << 3);
                ldmat_x4_t(smem_u32(&Vs[krh * VPITCH + nc]), vh_);
                ldmat_x4_t(smem_u32(&Vs[(64 + krh) * VPITCH + nc]), vl_);
                mma_bf16(oacc[2 * p],     ah, &vh_[0]);
                mma_bf16(oacc[2 * p + 1], ah, &vh_[2]);
                mma_bf16(oacc[2 * p],     al, &vh_[0]);
                mma_bf16(oacc[2 * p + 1], al, &vh_[2]);
                mma_bf16(oacc[2 * p],     ah, &vl_[0]);
                mma_bf16(oacc[2 * p + 1], ah, &vl_[2]);
            }
        }
    }

    // store O: warp's m16 strip x d64
    const int b = bh >> 4, h = bh & 15;
#pragma unroll
    for (int nt = 0; nt < 8; nt++)
#pragma unroll
        for (int rp = 0; rp < 2; rp++) {
            int row = qBase + warp * 16 + g + rp * 8;
            int d0 = nt * 8 + 2 * tig;
            float2 fv;
            fv.x = oacc[nt][rp * 2];
            fv.y = oacc[nt][rp * 2 + 1];
            *(float2*)&attn[((size_t)b * SEQ + row) * ETOT + h * HDIM + d0] = fv;
        }
}

// ---------------- layernorm + gate; writes split bf16 gate ----------------
__global__ __launch_bounds__(256) void ln_gate(
    const float* __restrict__ a, const float* __restrict__ u,
    const float* __restrict__ gamma, const float* __restrict__ beta,
    __nv_bfloat16* __restrict__ o2)
{
    const int row = blockIdx.x;
    const int tid = threadIdx.x;
    const float* ar = a + (size_t)row * ETOT;
    float4 xv = *(const float4*)&ar[tid * 4];

    float s1 = xv.x + xv.y + xv.z + xv.w;
    float s2 = xv.x * xv.x + xv.y * xv.y + xv.z * xv.z + xv.w * xv.w;
#pragma unroll
    for (int o = 16; o > 0; o >>= 1) {
        s1 += __shfl_xor_sync(0xffffffffu, s1, o);
        s2 += __shfl_xor_sync(0xffffffffu, s2, o);
    }
    __shared__ float r1[8], r2[8];
    __shared__ float mu_s, inv_s;
    if ((tid & 31) == 0) { r1[tid >> 5] = s1; r2[tid >> 5] = s2; }
    __syncthreads();
    if (tid == 0) {
        float t1 = 0.f, t2 = 0.f;
#pragma unroll
        for (int i = 0; i < 8; i++) { t1 += r1[i]; t2 += r2[i]; }
        float mu = t1 * (1.f / ETOT);
        float var = t2 * (1.f / ETOT) - mu * mu;
        mu_s = mu;
        inv_s = rsqrtf(var + 1e-5f);
    }
    __syncthreads();
    const float mu = mu_s, inv = inv_s;

    float4 gv = *(const float4*)&gamma[tid * 4];
    float4 bv = *(const float4*)&beta[tid * 4];
    float4 uv = *(const float4*)&u[(size_t)row * ETOT + tid * 4];
    float o0 = ((xv.x - mu) * inv * gv.x + bv.x) * uv.x;
    float o1 = ((xv.y - mu) * inv * gv.y + bv.y) * uv.y;
    float o2v = ((xv.z - mu) * inv * gv.z + bv.z) * uv.z;
    float o3 = ((xv.w - mu) * inv * gv.w + bv.w) * uv.w;
    __nv_bfloat16 h0, h1, h2, h3, l0, l1, l2, l3;
    split_bf16(o0, h0, l0); split_bf16(o1, h1, l1);
    split_bf16(o2v, h2, l2); split_bf16(o3, h3, l3);
    uint2 hv; hv.x = pack2(h0, h1); hv.y = pack2(h2, h3);
    uint2 lv; lv.x = pack2(l0, l1); lv.y = pack2(l2, l3);
    *(uint2*)&o2[(size_t)row * 2048 + tid * 4]        = hv;
    *(uint2*)&o2[(size_t)row * 2048 + 1024 + tid * 4] = lv;
}

// ---------------- launch ----------------
extern "C" void kernel_launch(void* const* d_in, const int* in_sizes, int n_in,
                              void* d_out, int out_size)
{
    const float* x    = (const float*)d_in[0];
    const float* Wq   = (const float*)d_in[1];
    const float* bq   = (const float*)d_in[2];
    const float* Wk   = (const float*)d_in[3];
    const float* bk   = (const float*)d_in[4];
    const float* Wv   = (const float*)d_in[5];
    const float* bv   = (const float*)d_in[6];
    const float* Wu   = (const float*)d_in[7];
    const float* bu   = (const float*)d_in[8];
    const float* Wo   = (const float*)d_in[9];
    const float* bo   = (const float*)d_in[10];
    const float* ln_g = (const float*)d_in[11];
    const float* ln_b = (const float*)d_in[12];

    __nv_bfloat16 *x2, *w5, *g2, *q2, *k2, *v2;
    float *up, *ap;
    cudaGetSymbolAddress((void**)&x2, g_x2);
    cudaGetSymbolAddress((void**)&w5, g_w5);
    cudaGetSymbolAddress((void**)&g2, g_g2);
    cudaGetSymbolAddress((void**)&q2, g_q2);
    cudaGetSymbolAddress((void**)&k2, g_k2);
    cudaGetSymbolAddress((void**)&v2, g_v2);
    cudaGetSymbolAddress((void**)&up, g_u);
    cudaGetSymbolAddress((void**)&ap, g_attn);

    cudaFuncSetAttribute(proj_fused,
                         cudaFuncAttributeMaxDynamicSharedMemorySize, PROJ_SMEM);
    cudaFuncSetAttribute(proj_out,
                         cudaFuncAttributeMaxDynamicSharedMemorySize, PROJ_SMEM);
    cudaFuncSetAttribute(attn_mma3,
                         cudaFuncAttributeMaxDynamicSharedMemorySize, ATTN_SMEM);

    split_all_kernel<<<9216, 256>>>(x, Wq, Wk, Wv, Wu, Wo, x2, w5);

    proj_fused<<<dim3(32, 32), 256, PROJ_SMEM>>>(
        x2, w5, bq, bk, bv, bu, q2, k2, v2, up);

    attn_mma3<<<dim3(SEQ / 128, 32), 256, ATTN_SMEM>>>(q2, k2, v2, ap);

    ln_gate<<<MTOT, 256>>>(ap, up, ln_g, ln_b, g2);

    proj_out<<<dim3(8, 32), 256, PROJ_SMEM>>>(
        g2, w5 + (size_t)4096 * 2048, bo, (float*)d_out);
}

// round 10
// speedup vs baseline: 3.5823x; 1.1510x over previous
#include <cuda_runtime.h>
#include <cuda_bf16.h>
#include <stdint.h>
#include <math.h>

// Problem dims (fixed)
#define MTOT 4096   // B*N
#define ETOT 1024
#define SEQ  2048
#define NH   16
#define HDIM 64

// ---------------- scratch (device globals) ----------------
__device__ __nv_bfloat16 g_x2[4096 * 2048];        // x split  [4096][hi 1024 | lo 1024]
__device__ __nv_bfloat16 g_w5[5120 * 2048];        // W splits packed rows: q,k,v,u,o
__device__ __nv_bfloat16 g_g2[4096 * 2048];        // gate split [hi|lo]
__device__ __nv_bfloat16 g_q2[32 * 2048 * 128];    // [bh][n][hi 64 | lo 64]
__device__ __nv_bfloat16 g_k2[32 * 2048 * 128];
__device__ __nv_bfloat16 g_v2[32 * 2048 * 128];
__device__ float g_u[4096 * 1024];
__device__ float g_attn[4096 * 1024];

// ---------------- helpers ----------------
__device__ __forceinline__ unsigned smem_u32(const void* p) {
    return (unsigned)__cvta_generic_to_shared(p);
}
__device__ __forceinline__ void ldmat_x4(unsigned addr, unsigned* r) {
    asm volatile("ldmatrix.sync.aligned.m8n8.x4.shared.b16 {%0,%1,%2,%3}, [%4];\n"
                 : "=r"(r[0]), "=r"(r[1]), "=r"(r[2]), "=r"(r[3]) : "r"(addr));
}
__device__ __forceinline__ void ldmat_x4_t(unsigned addr, unsigned* r) {
    asm volatile("ldmatrix.sync.aligned.m8n8.x4.trans.shared.b16 {%0,%1,%2,%3}, [%4];\n"
                 : "=r"(r[0]), "=r"(r[1]), "=r"(r[2]), "=r"(r[3]) : "r"(addr));
}
__device__ __forceinline__ void mma_bf16(float* c, const unsigned* a, const unsigned* b) {
    asm volatile(
        "mma.sync.aligned.m16n8k16.row.col.f32.bf16.bf16.f32 "
        "{%0,%1,%2,%3}, {%4,%5,%6,%7}, {%8,%9}, {%0,%1,%2,%3};\n"
        : "+f"(c[0]), "+f"(c[1]), "+f"(c[2]), "+f"(c[3])
        : "r"(a[0]), "r"(a[1]), "r"(a[2]), "r"(a[3]), "r"(b[0]), "r"(b[1]));
}
__device__ __forceinline__ void split_bf16(float x, __nv_bfloat16& hi, __nv_bfloat16& lo) {
    hi = __float2bfloat16(x);
    lo = __float2bfloat16(x - __bfloat162float(hi));
}
__device__ __forceinline__ unsigned pack2(__nv_bfloat16 a, __nv_bfloat16 b) {
    __nv_bfloat162 t; t.x = a; t.y = b;
    return *(unsigned*)&t;
}
__device__ __forceinline__ void cp16(unsigned dst, const void* src) {
    asm volatile("cp.async.cg.shared.global [%0], [%1], 16;\n" :: "r"(dst), "l"(src));
}
__device__ __forceinline__ void cp_commit() { asm volatile("cp.async.commit_group;\n"); }
__device__ __forceinline__ void cp_wait0()  { asm volatile("cp.async.wait_group 0;\n" ::: "memory"); }
__device__ __forceinline__ void cp_wait1()  { asm volatile("cp.async.wait_group 1;\n" ::: "memory"); }

// ---------------- unified split: x + 5 weights, one launch ----------------
__global__ __launch_bounds__(256) void split_all_kernel(
    const float* __restrict__ x,
    const float* __restrict__ w0, const float* __restrict__ w1,
    const float* __restrict__ w2, const float* __restrict__ w3,
    const float* __restrict__ w4,
    __nv_bfloat16* __restrict__ outX, __nv_bfloat16* __restrict__ outW)
{
    int row = blockIdx.x;
    int c = threadIdx.x << 2;
    const float* src;
    __nv_bfloat16* dst;
    if (row < 4096) {
        src = x + (size_t)row * 1024;
        dst = outX + (size_t)row * 2048;
    } else {
        int wrow = row - 4096;
        int which = wrow >> 10;
        int r = wrow & 1023;
        const float* w = (which == 0) ? w0 : (which == 1) ? w1 :
                         (which == 2) ? w2 : (which == 3) ? w3 : w4;
        src = w + (size_t)r * 1024;
        dst = outW + (size_t)wrow * 2048;
    }
    float4 a = *(const float4*)&src[c];
    __nv_bfloat16 h0, h1, h2, h3, l0, l1, l2, l3;
    split_bf16(a.x, h0, l0); split_bf16(a.y, h1, l1);
    split_bf16(a.z, h2, l2); split_bf16(a.w, h3, l3);
    uint2 hv; hv.x = pack2(h0, h1); hv.y = pack2(h2, h3);
    uint2 lv; lv.x = pack2(l0, l1); lv.y = pack2(l2, l3);
    *(uint2*)&dst[c] = hv;
    *(uint2*)&dst[1024 + c] = lv;
}

// ================= projection GEMM core (2-stage cp.async, 2 CTAs/SM) =================
#define PPITCH 72
#define PSTG_ELEM (2 * 128 * PPITCH)          // bf16 elems per stage (A+B)
#define PROJ_SMEM (2 * PSTG_ELEM * 2)         // 73,728 B -> 2 CTAs/SM

__device__ __forceinline__ void proj_load_chunk(
    const __nv_bfloat16* __restrict__ A2, const __nv_bfloat16* __restrict__ B2,
    __nv_bfloat16* As, __nv_bfloat16* Bs, int mB, int nB, int kb, int tid)
{
#pragma unroll
    for (int t = 0; t < 4; t++) {
        int idx = tid + t * 256;            // 0..1023
        int row = idx >> 3, s = idx & 7;    // 8 x 16B slices per row
        int gcol = (s < 4) ? (kb + s * 8) : (1024 + kb + (s - 4) * 8);
        int scol = (s < 4) ? (s * 8) : (32 + (s - 4) * 8);
        cp16(smem_u32(&As[row * PPITCH + scol]), &A2[(size_t)(mB + row) * 2048 + gcol]);
        cp16(smem_u32(&Bs[row * PPITCH + scol]), &B2[(size_t)(nB + row) * 2048 + gcol]);
    }
}

__device__ __forceinline__ void proj_mainloop(
    const __nv_bfloat16* __restrict__ A2, const __nv_bfloat16* __restrict__ B2,
    __nv_bfloat16* smb, int mB, int nB, int tid, int lane,
    int warpM, int warpN, float acc[2][8][4])
{
#pragma unroll
    for (int mt = 0; mt < 2; mt++)
#pragma unroll
        for (int nt = 0; nt < 8; nt++)
#pragma unroll
            for (int r = 0; r < 4; r++) acc[mt][nt][r] = 0.f;

    __nv_bfloat16* stA[2] = { smb, smb + PSTG_ELEM };
    proj_load_chunk(A2, B2, stA[0], stA[0] + 128 * PPITCH, mB, nB, 0, tid);
    cp_commit();

    for (int c = 0; c < 32; c++) {
        const int buf = c & 1;
        cp_wait0();        // chunk c complete (c+1 not yet issued)
        __syncthreads();   // all warps done computing on buf^1 (chunk c-1)
        if (c + 1 < 32) {
            __nv_bfloat16* st = stA[buf ^ 1];
            proj_load_chunk(A2, B2, st, st + 128 * PPITCH, mB, nB, (c + 1) * 32, tid);
            cp_commit();   // overlaps this chunk's compute
        }

        const __nv_bfloat16* As = stA[buf];
        const __nv_bfloat16* Bs = As + 128 * PPITCH;
#pragma unroll
        for (int ks = 0; ks < 2; ks++) {
            const int kk = ks * 16;
            unsigned ahi[2][4], alo[2][4];
#pragma unroll
            for (int mt = 0; mt < 2; mt++) {
                int arow = warpM * 32 + mt * 16 + (lane & 15);
                int ako = kk + ((lane >> 4) << 3);
                ldmat_x4(smem_u32(&As[arow * PPITCH + ako]), ahi[mt]);
                ldmat_x4(smem_u32(&As[arow * PPITCH + 32 + ako]), alo[mt]);
            }
#pragma unroll
            for (int p = 0; p < 4; p++) {
                unsigned bh_[4], bl_[4];
                int nrow = warpN * 64 + p * 16 + ((lane >> 4) << 3) + (lane & 7);
                int kc = kk + (((lane >> 3) & 1) << 3);
                ldmat_x4(smem_u32(&Bs[nrow * PPITCH + kc]), bh_);
                ldmat_x4(smem_u32(&Bs[nrow * PPITCH + 32 + kc]), bl_);
#pragma unroll
                for (int mt = 0; mt < 2; mt++) {
                    mma_bf16(acc[mt][2 * p],     ahi[mt], &bh_[0]);
                    mma_bf16(acc[mt][2 * p + 1], ahi[mt], &bh_[2]);
                }
#pragma unroll
                for (int mt = 0; mt < 2; mt++) {
                    mma_bf16(acc[mt][2 * p],     alo[mt], &bh_[0]);
                    mma_bf16(acc[mt][2 * p + 1], alo[mt], &bh_[2]);
                }
#pragma unroll
                for (int mt = 0; mt < 2; mt++) {
                    mma_bf16(acc[mt][2 * p],     ahi[mt], &bl_[0]);
                    mma_bf16(acc[mt][2 * p + 1], ahi[mt], &bl_[2]);
                }
            }
        }
    }
}

// ---- fused Q/K/V/U projection: grid (32,32) ----
__global__ __launch_bounds__(256, 2) void proj_fused(
    const __nv_bfloat16* __restrict__ A2, const __nv_bfloat16* __restrict__ W2,
    const float* __restrict__ b0, const float* __restrict__ b1,
    const float* __restrict__ b2, const float* __restrict__ b3,
    __nv_bfloat16* __restrict__ outQ, __nv_bfloat16* __restrict__ outK,
    __nv_bfloat16* __restrict__ outV, float* __restrict__ outU)
{
    extern __shared__ __nv_bfloat16 smb[];
    const int tid = threadIdx.x;
    const int lane = tid & 31, warp = tid >> 5;
    const int warpM = warp >> 1, warpN = warp & 1;
    const int mB = blockIdx.y * 128, nB = blockIdx.x * 128;
    const int g = lane >> 2, tig = lane & 3;
    const int which = nB >> 10;

    float acc[2][8][4];
    proj_mainloop(A2, W2, smb, mB, nB, tid, lane, warpM, warpN, acc);

    const float* bp = (which == 0) ? b0 : (which == 1) ? b1 : (which == 2) ? b2 : b3;
    __nv_bfloat16* outH = (which == 0) ? outQ : (which == 1) ? outK : outV;
    const int act = (which >= 2);

#pragma unroll
    for (int mt = 0; mt < 2; mt++)
#pragma unroll
        for (int nt = 0; nt < 8; nt++)
#pragma unroll
            for (int rp = 0; rp < 2; rp++) {
                int m = mB + warpM * 32 + mt * 16 + g + rp * 8;
                int e0 = nB + warpN * 64 + nt * 8 + 2 * tig;
                int eq = e0 & 1023;
                float v0 = acc[mt][nt][rp * 2]     + __ldg(&bp[eq]);
                float v1 = acc[mt][nt][rp * 2 + 1] + __ldg(&bp[eq + 1]);
                if (act) {
                    v0 = v0 / (1.f + __expf(-v0));
                    v1 = v1 / (1.f + __expf(-v1));
                }
                if (which == 3) {
                    float2 fv; fv.x = v0; fv.y = v1;
                    *(float2*)&outU[(size_t)m * ETOT + eq] = fv;
                } else {
                    int b = m >> 11, n = m & (SEQ - 1);
                    int h = eq >> 6, d = eq & (HDIM - 1);
                    __nv_bfloat16 h0, h1, l0, l1;
                    split_bf16(v0, h0, l0);
                    split_bf16(v1, h1, l1);
                    size_t base = (((size_t)b * NH + h) * SEQ + n) * 128 + d;
                    *(unsigned*)&outH[base]      = pack2(h0, h1);
                    *(unsigned*)&outH[base + 64] = pack2(l0, l1);
                }
            }
}

// ---- output projection: grid (8,32) ----
__global__ __launch_bounds__(256, 2) void proj_out(
    const __nv_bfloat16* __restrict__ A2, const __nv_bfloat16* __restrict__ W2,
    const float* __restrict__ bias, float* __restrict__ outF)
{
    extern __shared__ __nv_bfloat16 smb[];
    const int tid = threadIdx.x;
    const int lane = tid & 31, warp = tid >> 5;
    const int warpM = warp >> 1, warpN = warp & 1;
    const int mB = blockIdx.y * 128, nB = blockIdx.x * 128;
    const int g = lane >> 2, tig = lane & 3;

    float acc[2][8][4];
    proj_mainloop(A2, W2, smb, mB, nB, tid, lane, warpM, warpN, acc);

#pragma unroll
    for (int mt = 0; mt < 2; mt++)
#pragma unroll
        for (int nt = 0; nt < 8; nt++)
#pragma unroll
            for (int rp = 0; rp < 2; rp++) {
                int m = mB + warpM * 32 + mt * 16 + g + rp * 8;
                int e0 = nB + warpN * 64 + nt * 8 + 2 * tig;
                float2 fv;
                fv.x = acc[mt][nt][rp * 2]     + __ldg(&bias[e0]);
                fv.y = acc[mt][nt][rp * 2 + 1] + __ldg(&bias[e0 + 1]);
                *(float2*)&outF[(size_t)m * ETOT + e0] = fv;
            }
}

// ================= attention: S-in-registers, double-buffered K/V =================
#define QPITCH 136
#define VPITCH 72
#define KS_ELEM (64 * QPITCH)
#define VS_ELEM (128 * VPITCH)
#define ATTN_SMEM ((128 * QPITCH + 2 * KS_ELEM + 2 * VS_ELEM) * 2)

__device__ __forceinline__ void attn_load_kv(
    const __nv_bfloat16* kp, const __nv_bfloat16* vp,
    __nv_bfloat16* Ks, __nv_bfloat16* Vs, int kt, int tid)
{
#pragma unroll
    for (int t = 0; t < 4; t++) {
        int idx = tid + t * 256;
        int row = idx >> 4, s = idx & 15;
        cp16(smem_u32(&Ks[row * QPITCH + s * 8]), &kp[(size_t)(kt + row) * 128 + s * 8]);
        if (s < 8)
            cp16(smem_u32(&Vs[row * VPITCH + s * 8]), &vp[(size_t)(kt + row) * 128 + s * 8]);
        else
            cp16(smem_u32(&Vs[(64 + row) * VPITCH + (s - 8) * 8]),
                 &vp[(size_t)(kt + row) * 128 + s * 8]);
    }
}

__global__ __launch_bounds__(256, 2) void attn_mma3(
    const __nv_bfloat16* __restrict__ q2, const __nv_bfloat16* __restrict__ k2,
    const __nv_bfloat16* __restrict__ v2, float* __restrict__ attn)
{
    extern __shared__ __nv_bfloat16 smb[];
    __nv_bfloat16* Qs  = smb;                       // [128][136]
    __nv_bfloat16* Ks0 = Qs + 128 * QPITCH;         // [2][64][136]
    __nv_bfloat16* Vs0 = Ks0 + 2 * KS_ELEM;         // [2][128][72]

    const int tid = threadIdx.x;
    const int lane = tid & 31, warp = tid >> 5;     // warp 0..7 = m16 strip
    const int g = lane >> 2, tig = lane & 3;
    const int sel = lane >> 3, l8 = lane & 7;
    const int bh = blockIdx.y;
    const int qBase = blockIdx.x * 128;
    const __nv_bfloat16* qp = q2 + (size_t)bh * SEQ * 128;
    const __nv_bfloat16* kp = k2 + (size_t)bh * SEQ * 128;
    const __nv_bfloat16* vp = v2 + (size_t)bh * SEQ * 128;

    // Q (persistent)
#pragma unroll
    for (int t = 0; t < 8; t++) {
        int idx = tid + t * 256;
        int row = idx >> 4, s = idx & 15;
        cp16(smem_u32(&Qs[row * QPITCH + s * 8]), &qp[(size_t)(qBase + row) * 128 + s * 8]);
    }
    cp_commit();
    attn_load_kv(kp, vp, Ks0, Vs0, 0, tid);
    cp_commit();

    float oacc[8][4];
#pragma unroll
    for (int nt = 0; nt < 8; nt++)
#pragma unroll
        for (int r = 0; r < 4; r++) oacc[nt][r] = 0.f;

    for (int tile = 0; tile < 32; tile++) {
        const int buf = tile & 1;
        cp_wait0();
        __syncthreads();
        if (tile + 1 < 32) {
            attn_load_kv(kp, vp, Ks0 + (buf ^ 1) * KS_ELEM, Vs0 + (buf ^ 1) * VS_ELEM,
                         (tile + 1) * 64, tid);
            cp_commit();
        }
        const __nv_bfloat16* Ks = Ks0 + buf * KS_ELEM;
        const __nv_bfloat16* Vs = Vs0 + buf * VS_ELEM;

        // ---- phase 2: S[m16][64] = Q K^T (3-term) ----
        float sacc[8][4];
#pragma unroll
        for (int nt = 0; nt < 8; nt++)
#pragma unroll
            for (int r = 0; r < 4; r++) sacc[nt][r] = 0.f;

#pragma unroll
        for (int ks = 0; ks < 4; ks++) {
            const int kk = ks * 16;
            unsigned qhi[4], qlo[4];
            int arow = warp * 16 + (lane & 15);
            int ako = kk + ((lane >> 4) << 3);
            ldmat_x4(smem_u32(&Qs[arow * QPITCH + ako]), qhi);
            ldmat_x4(smem_u32(&Qs[arow * QPITCH + 64 + ako]), qlo);
#pragma unroll
            for (int p = 0; p < 4; p++) {
                unsigned kh_[4], kl_[4];
                int jrow = p * 16 + ((lane >> 4) << 3) + (lane & 7);
                int kc = kk + (((lane >> 3) & 1) << 3);
                ldmat_x4(smem_u32(&Ks[jrow * QPITCH + kc]), kh_);
                ldmat_x4(smem_u32(&Ks[jrow * QPITCH + 64 + kc]), kl_);
                mma_bf16(sacc[2 * p],     qhi, &kh_[0]);
                mma_bf16(sacc[2 * p + 1], qhi, &kh_[2]);
                mma_bf16(sacc[2 * p],     qlo, &kh_[0]);
                mma_bf16(sacc[2 * p + 1], qlo, &kh_[2]);
                mma_bf16(sacc[2 * p],     qhi, &kl_[0]);
                mma_bf16(sacc[2 * p + 1], qhi, &kl_[2]);
            }
        }

        // ---- phase 3: O += S V, S converted in registers per k16-chunk ----
#pragma unroll
        for (int t = 0; t < 4; t++) {
            unsigned ah[4], al[4];
#pragma unroll
            for (int j = 0; j < 2; j++) {
                float* s = sacc[2 * t + j];
                float s0 = s[0] * 0.125f, s1 = s[1] * 0.125f;
                float s2 = s[2] * 0.125f, s3 = s[3] * 0.125f;
                s0 = s0 > 0.f ? s0 : 0.f;  s1 = s1 > 0.f ? s1 : 0.f;
                s2 = s2 > 0.f ? s2 : 0.f;  s3 = s3 > 0.f ? s3 : 0.f;
                __nv_bfloat16 h0, h1, h2, h3, l0, l1, l2, l3;
                split_bf16(s0, h0, l0); split_bf16(s1, h1, l1);
                split_bf16(s2, h2, l2); split_bf16(s3, h3, l3);
                ah[2 * j]     = pack2(h0, h1);
                ah[2 * j + 1] = pack2(h2, h3);
                al[2 * j]     = pack2(l0, l1);
                al[2 * j + 1] = pack2(l2, l3);
            }
#pragma unroll
            for (int p = 0; p < 4; p++) {
                unsigned vh_[4], vl_[4];
                int krh = t * 16 + ((sel & 1) << 3) + l8;
                int nc = p * 16 + ((sel >> 1) << 3);
                ldmat_x4_t(smem_u32(&Vs[krh * VPITCH + nc]), vh_);
                ldmat_x4_t(smem_u32(&Vs[(64 + krh) * VPITCH + nc]), vl_);
                mma_bf16(oacc[2 * p],     ah, &vh_[0]);
                mma_bf16(oacc[2 * p + 1], ah, &vh_[2]);
                mma_bf16(oacc[2 * p],     al, &vh_[0]);
                mma_bf16(oacc[2 * p + 1], al, &vh_[2]);
                mma_bf16(oacc[2 * p],     ah, &vl_[0]);
                mma_bf16(oacc[2 * p + 1], ah, &vl_[2]);
            }
        }
    }

    const int b = bh >> 4, h = bh & 15;
#pragma unroll
    for (int nt = 0; nt < 8; nt++)
#pragma unroll
        for (int rp = 0; rp < 2; rp++) {
            int row = qBase + warp * 16 + g + rp * 8;
            int d0 = nt * 8 + 2 * tig;
            float2 fv;
            fv.x = oacc[nt][rp * 2];
            fv.y = oacc[nt][rp * 2 + 1];
            *(float2*)&attn[((size_t)b * SEQ + row) * ETOT + h * HDIM + d0] = fv;
        }
}

// ---------------- layernorm + gate; writes split bf16 gate ----------------
__global__ __launch_bounds__(256) void ln_gate(
    const float* __restrict__ a, const float* __restrict__ u,
    const float* __restrict__ gamma, const float* __restrict__ beta,
    __nv_bfloat16* __restrict__ o2)
{
    const int row = blockIdx.x;
    const int tid = threadIdx.x;
    const float* ar = a + (size_t)row * ETOT;
    float4 xv = *(const float4*)&ar[tid * 4];

    float s1 = xv.x + xv.y + xv.z + xv.w;
    float s2 = xv.x * xv.x + xv.y * xv.y + xv.z * xv.z + xv.w * xv.w;
#pragma unroll
    for (int o = 16; o > 0; o >>= 1) {
        s1 += __shfl_xor_sync(0xffffffffu, s1, o);
        s2 += __shfl_xor_sync(0xffffffffu, s2, o);
    }
    __shared__ float r1[8], r2[8];
    __shared__ float mu_s, inv_s;
    if ((tid & 31) == 0) { r1[tid >> 5] = s1; r2[tid >> 5] = s2; }
    __syncthreads();
    if (tid == 0) {
        float t1 = 0.f, t2 = 0.f;
#pragma unroll
        for (int i = 0; i < 8; i++) { t1 += r1[i]; t2 += r2[i]; }
        float mu = t1 * (1.f / ETOT);
        float var = t2 * (1.f / ETOT) - mu * mu;
        mu_s = mu;
        inv_s = rsqrtf(var + 1e-5f);
    }
    __syncthreads();
    const float mu = mu_s, inv = inv_s;

    float4 gv = *(const float4*)&gamma[tid * 4];
    float4 bv = *(const float4*)&beta[tid * 4];
    float4 uv = *(const float4*)&u[(size_t)row * ETOT + tid * 4];
    float o0 = ((xv.x - mu) * inv * gv.x + bv.x) * uv.x;
    float o1 = ((xv.y - mu) * inv * gv.y + bv.y) * uv.y;
    float o2v = ((xv.z - mu) * inv * gv.z + bv.z) * uv.z;
    float o3 = ((xv.w - mu) * inv * gv.w + bv.w) * uv.w;
    __nv_bfloat16 h0, h1, h2, h3, l0, l1, l2, l3;
    split_bf16(o0, h0, l0); split_bf16(o1, h1, l1);
    split_bf16(o2v, h2, l2); split_bf16(o3, h3, l3);
    uint2 hv; hv.x = pack2(h0, h1); hv.y = pack2(h2, h3);
    uint2 lv; lv.x = pack2(l0, l1); lv.y = pack2(l2, l3);
    *(uint2*)&o2[(size_t)row * 2048 + tid * 4]        = hv;
    *(uint2*)&o2[(size_t)row * 2048 + 1024 + tid * 4] = lv;
}

// ---------------- launch ----------------
extern "C" void kernel_launch(void* const* d_in, const int* in_sizes, int n_in,
                              void* d_out, int out_size)
{
    const float* x    = (const float*)d_in[0];
    const float* Wq   = (const float*)d_in[1];
    const float* bq   = (const float*)d_in[2];
    const float* Wk   = (const float*)d_in[3];
    const float* bk   = (const float*)d_in[4];
    const float* Wv   = (const float*)d_in[5];
    const float* bv   = (const float*)d_in[6];
    const float* Wu   = (const float*)d_in[7];
    const float* bu   = (const float*)d_in[8];
    const float* Wo   = (const float*)d_in[9];
    const float* bo   = (const float*)d_in[10];
    const float* ln_g = (const float*)d_in[11];
    const float* ln_b = (const float*)d_in[12];

    __nv_bfloat16 *x2, *w5, *g2, *q2, *k2, *v2;
    float *up, *ap;
    cudaGetSymbolAddress((void**)&x2, g_x2);
    cudaGetSymbolAddress((void**)&w5, g_w5);
    cudaGetSymbolAddress((void**)&g2, g_g2);
    cudaGetSymbolAddress((void**)&q2, g_q2);
    cudaGetSymbolAddress((void**)&k2, g_k2);
    cudaGetSymbolAddress((void**)&v2, g_v2);
    cudaGetSymbolAddress((void**)&up, g_u);
    cudaGetSymbolAddress((void**)&ap, g_attn);

    cudaFuncSetAttribute(proj_fused,
                         cudaFuncAttributeMaxDynamicSharedMemorySize, PROJ_SMEM);
    cudaFuncSetAttribute(proj_out,
                         cudaFuncAttributeMaxDynamicSharedMemorySize, PROJ_SMEM);
    cudaFuncSetAttribute(attn_mma3,
                         cudaFuncAttributeMaxDynamicSharedMemorySize, ATTN_SMEM);

    split_all_kernel<<<9216, 256>>>(x, Wq, Wk, Wv, Wu, Wo, x2, w5);

    proj_fused<<<dim3(32, 32), 256, PROJ_SMEM>>>(
        x2, w5, bq, bk, bv, bu, q2, k2, v2, up);

    attn_mma3<<<dim3(SEQ / 128, 32), 256, ATTN_SMEM>>>(q2, k2, v2, ap);

    ln_gate<<<MTOT, 256>>>(ap, up, ln_g, ln_b, g2);

    proj_out<<<dim3(8, 32), 256, PROJ_SMEM>>>(
        g2, w5 + (size_t)4096 * 2048, bo, (float*)d_out);
}

// round 11
// speedup vs baseline: 3.5876x; 1.0015x over previous
#include <cuda_runtime.h>
#include <cuda_bf16.h>
#include <stdint.h>
#include <math.h>

// Problem dims (fixed)
#define MTOT 4096   // B*N
#define ETOT 1024
#define SEQ  2048
#define NH   16
#define HDIM 64

// ---------------- scratch (device globals) ----------------
__device__ __nv_bfloat16 g_x2[4096 * 2048];        // x split  [4096][hi 1024 | lo 1024]
__device__ __nv_bfloat16 g_w5[5120 * 2048];        // W splits packed rows: q,k,v,u,o
__device__ __nv_bfloat16 g_g2[4096 * 2048];        // gate split [hi|lo]
__device__ __nv_bfloat16 g_q2[32 * 2048 * 128];    // [bh][n][hi 64 | lo 64]
__device__ __nv_bfloat16 g_k2[32 * 2048 * 128];
__device__ __nv_bfloat16 g_v2[32 * 2048 * 128];
__device__ float g_u[4096 * 1024];
__device__ float g_attn[4096 * 1024];

// ---------------- helpers ----------------
__device__ __forceinline__ unsigned smem_u32(const void* p) {
    return (unsigned)__cvta_generic_to_shared(p);
}
__device__ __forceinline__ void ldmat_x4(unsigned addr, unsigned* r) {
    asm volatile("ldmatrix.sync.aligned.m8n8.x4.shared.b16 {%0,%1,%2,%3}, [%4];\n"
                 : "=r"(r[0]), "=r"(r[1]), "=r"(r[2]), "=r"(r[3]) : "r"(addr));
}
__device__ __forceinline__ void ldmat_x4_t(unsigned addr, unsigned* r) {
    asm volatile("ldmatrix.sync.aligned.m8n8.x4.trans.shared.b16 {%0,%1,%2,%3}, [%4];\n"
                 : "=r"(r[0]), "=r"(r[1]), "=r"(r[2]), "=r"(r[3]) : "r"(addr));
}
__device__ __forceinline__ void mma_bf16(float* c, const unsigned* a, const unsigned* b) {
    asm volatile(
        "mma.sync.aligned.m16n8k16.row.col.f32.bf16.bf16.f32 "
        "{%0,%1,%2,%3}, {%4,%5,%6,%7}, {%8,%9}, {%0,%1,%2,%3};\n"
        : "+f"(c[0]), "+f"(c[1]), "+f"(c[2]), "+f"(c[3])
        : "r"(a[0]), "r"(a[1]), "r"(a[2]), "r"(a[3]), "r"(b[0]), "r"(b[1]));
}
__device__ __forceinline__ void split_bf16(float x, __nv_bfloat16& hi, __nv_bfloat16& lo) {
    hi = __float2bfloat16(x);
    lo = __float2bfloat16(x - __bfloat162float(hi));
}
__device__ __forceinline__ unsigned pack2(__nv_bfloat16 a, __nv_bfloat16 b) {
    __nv_bfloat162 t; t.x = a; t.y = b;
    return *(unsigned*)&t;
}
__device__ __forceinline__ void cp16(unsigned dst, const void* src) {
    asm volatile("cp.async.cg.shared.global [%0], [%1], 16;\n" :: "r"(dst), "l"(src));
}
__device__ __forceinline__ void cp_commit() { asm volatile("cp.async.commit_group;\n"); }
__device__ __forceinline__ void cp_wait0()  { asm volatile("cp.async.wait_group 0;\n" ::: "memory"); }
__device__ __forceinline__ void cp_wait1()  { asm volatile("cp.async.wait_group 1;\n" ::: "memory"); }

// ---------------- unified split: x + 5 weights, one launch ----------------
__global__ __launch_bounds__(256) void split_all_kernel(
    const float* __restrict__ x,
    const float* __restrict__ w0, const float* __restrict__ w1,
    const float* __restrict__ w2, const float* __restrict__ w3,
    const float* __restrict__ w4,
    __nv_bfloat16* __restrict__ outX, __nv_bfloat16* __restrict__ outW)
{
    int row = blockIdx.x;
    int c = threadIdx.x << 2;
    const float* src;
    __nv_bfloat16* dst;
    if (row < 4096) {
        src = x + (size_t)row * 1024;
        dst = outX + (size_t)row * 2048;
    } else {
        int wrow = row - 4096;
        int which = wrow >> 10;
        int r = wrow & 1023;
        const float* w = (which == 0) ? w0 : (which == 1) ? w1 :
                         (which == 2) ? w2 : (which == 3) ? w3 : w4;
        src = w + (size_t)r * 1024;
        dst = outW + (size_t)wrow * 2048;
    }
    float4 a = *(const float4*)&src[c];
    __nv_bfloat16 h0, h1, h2, h3, l0, l1, l2, l3;
    split_bf16(a.x, h0, l0); split_bf16(a.y, h1, l1);
    split_bf16(a.z, h2, l2); split_bf16(a.w, h3, l3);
    uint2 hv; hv.x = pack2(h0, h1); hv.y = pack2(h2, h3);
    uint2 lv; lv.x = pack2(l0, l1); lv.y = pack2(l2, l3);
    *(uint2*)&dst[c] = hv;
    *(uint2*)&dst[1024 + c] = lv;
}

// ================= projection GEMM core (2-stage cp.async, 2 CTAs/SM) =================
#define PPITCH 72
#define PSTG_ELEM (2 * 128 * PPITCH)          // bf16 elems per stage (A+B)
#define PROJ_SMEM (2 * PSTG_ELEM * 2)         // 73,728 B -> 2 CTAs/SM

__device__ __forceinline__ void proj_load_chunk(
    const __nv_bfloat16* __restrict__ A2, const __nv_bfloat16* __restrict__ B2,
    __nv_bfloat16* As, __nv_bfloat16* Bs, int mB, int nB, int kb, int tid)
{
#pragma unroll
    for (int t = 0; t < 4; t++) {
        int idx = tid + t * 256;            // 0..1023
        int row = idx >> 3, s = idx & 7;    // 8 x 16B slices per row
        int gcol = (s < 4) ? (kb + s * 8) : (1024 + kb + (s - 4) * 8);
        int scol = (s < 4) ? (s * 8) : (32 + (s - 4) * 8);
        cp16(smem_u32(&As[row * PPITCH + scol]), &A2[(size_t)(mB + row) * 2048 + gcol]);
        cp16(smem_u32(&Bs[row * PPITCH + scol]), &B2[(size_t)(nB + row) * 2048 + gcol]);
    }
}

__device__ __forceinline__ void proj_mainloop(
    const __nv_bfloat16* __restrict__ A2, const __nv_bfloat16* __restrict__ B2,
    __nv_bfloat16* smb, int mB, int nB, int tid, int lane,
    int warpM, int warpN, float acc[2][8][4])
{
#pragma unroll
    for (int mt = 0; mt < 2; mt++)
#pragma unroll
        for (int nt = 0; nt < 8; nt++)
#pragma unroll
            for (int r = 0; r < 4; r++) acc[mt][nt][r] = 0.f;

    __nv_bfloat16* stA[2] = { smb, smb + PSTG_ELEM };
    proj_load_chunk(A2, B2, stA[0], stA[0] + 128 * PPITCH, mB, nB, 0, tid);
    cp_commit();

    for (int c = 0; c < 32; c++) {
        const int buf = c & 1;
        cp_wait0();        // chunk c complete (c+1 not yet issued)
        __syncthreads();   // all warps done computing on buf^1 (chunk c-1)
        if (c + 1 < 32) {
            __nv_bfloat16* st = stA[buf ^ 1];
            proj_load_chunk(A2, B2, st, st + 128 * PPITCH, mB, nB, (c + 1) * 32, tid);
            cp_commit();   // overlaps this chunk's compute
        }

        const __nv_bfloat16* As = stA[buf];
        const __nv_bfloat16* Bs = As + 128 * PPITCH;
#pragma unroll
        for (int ks = 0; ks < 2; ks++) {
            const int kk = ks * 16;
            unsigned ahi[2][4], alo[2][4];
#pragma unroll
            for (int mt = 0; mt < 2; mt++) {
                int arow = warpM * 32 + mt * 16 + (lane & 15);
                int ako = kk + ((lane >> 4) << 3);
                ldmat_x4(smem_u32(&As[arow * PPITCH + ako]), ahi[mt]);
                ldmat_x4(smem_u32(&As[arow * PPITCH + 32 + ako]), alo[mt]);
            }
#pragma unroll
            for (int p = 0; p < 4; p++) {
                unsigned bh_[4], bl_[4];
                int nrow = warpN * 64 + p * 16 + ((lane >> 4) << 3) + (lane & 7);
                int kc = kk + (((lane >> 3) & 1) << 3);
                ldmat_x4(smem_u32(&Bs[nrow * PPITCH + kc]), bh_);
                ldmat_x4(smem_u32(&Bs[nrow * PPITCH + 32 + kc]), bl_);
#pragma unroll
                for (int mt = 0; mt < 2; mt++) {
                    mma_bf16(acc[mt][2 * p],     ahi[mt], &bh_[0]);
                    mma_bf16(acc[mt][2 * p + 1], ahi[mt], &bh_[2]);
                }
#pragma unroll
                for (int mt = 0; mt < 2; mt++) {
                    mma_bf16(acc[mt][2 * p],     alo[mt], &bh_[0]);
                    mma_bf16(acc[mt][2 * p + 1], alo[mt], &bh_[2]);
                }
#pragma unroll
                for (int mt = 0; mt < 2; mt++) {
                    mma_bf16(acc[mt][2 * p],     ahi[mt], &bl_[0]);
                    mma_bf16(acc[mt][2 * p + 1], ahi[mt], &bl_[2]);
                }
            }
        }
    }
}

// ---- fused Q/K/V/U projection: grid (32,32) ----
__global__ __launch_bounds__(256, 2) void proj_fused(
    const __nv_bfloat16* __restrict__ A2, const __nv_bfloat16* __restrict__ W2,
    const float* __restrict__ b0, const float* __restrict__ b1,
    const float* __restrict__ b2, const float* __restrict__ b3,
    __nv_bfloat16* __restrict__ outQ, __nv_bfloat16* __restrict__ outK,
    __nv_bfloat16* __restrict__ outV, float* __restrict__ outU)
{
    extern __shared__ __nv_bfloat16 smb[];
    const int tid = threadIdx.x;
    const int lane = tid & 31, warp = tid >> 5;
    const int warpM = warp >> 1, warpN = warp & 1;
    const int mB = blockIdx.y * 128, nB = blockIdx.x * 128;
    const int g = lane >> 2, tig = lane & 3;
    const int which = nB >> 10;

    float acc[2][8][4];
    proj_mainloop(A2, W2, smb, mB, nB, tid, lane, warpM, warpN, acc);

    const float* bp = (which == 0) ? b0 : (which == 1) ? b1 : (which == 2) ? b2 : b3;
    __nv_bfloat16* outH = (which == 0) ? outQ : (which == 1) ? outK : outV;
    const int act = (which >= 2);

#pragma unroll
    for (int mt = 0; mt < 2; mt++)
#pragma unroll
        for (int nt = 0; nt < 8; nt++)
#pragma unroll
            for (int rp = 0; rp < 2; rp++) {
                int m = mB + warpM * 32 + mt * 16 + g + rp * 8;
                int e0 = nB + warpN * 64 + nt * 8 + 2 * tig;
                int eq = e0 & 1023;
                float v0 = acc[mt][nt][rp * 2]     + __ldg(&bp[eq]);
                float v1 = acc[mt][nt][rp * 2 + 1] + __ldg(&bp[eq + 1]);
                if (act) {
                    v0 = v0 / (1.f + __expf(-v0));
                    v1 = v1 / (1.f + __expf(-v1));
                }
                if (which == 3) {
                    float2 fv; fv.x = v0; fv.y = v1;
                    *(float2*)&outU[(size_t)m * ETOT + eq] = fv;
                } else {
                    int b = m >> 11, n = m & (SEQ - 1);
                    int h = eq >> 6, d = eq & (HDIM - 1);
                    __nv_bfloat16 h0, h1, l0, l1;
                    split_bf16(v0, h0, l0);
                    split_bf16(v1, h1, l1);
                    size_t base = (((size_t)b * NH + h) * SEQ + n) * 128 + d;
                    *(unsigned*)&outH[base]      = pack2(h0, h1);
                    *(unsigned*)&outH[base + 64] = pack2(l0, l1);
                }
            }
}

// ---- output projection: grid (8,32) ----
__global__ __launch_bounds__(256, 2) void proj_out(
    const __nv_bfloat16* __restrict__ A2, const __nv_bfloat16* __restrict__ W2,
    const float* __restrict__ bias, float* __restrict__ outF)
{
    extern __shared__ __nv_bfloat16 smb[];
    const int tid = threadIdx.x;
    const int lane = tid & 31, warp = tid >> 5;
    const int warpM = warp >> 1, warpN = warp & 1;
    const int mB = blockIdx.y * 128, nB = blockIdx.x * 128;
    const int g = lane >> 2, tig = lane & 3;

    float acc[2][8][4];
    proj_mainloop(A2, W2, smb, mB, nB, tid, lane, warpM, warpN, acc);

#pragma unroll
    for (int mt = 0; mt < 2; mt++)
#pragma unroll
        for (int nt = 0; nt < 8; nt++)
#pragma unroll
            for (int rp = 0; rp < 2; rp++) {
                int m = mB + warpM * 32 + mt * 16 + g + rp * 8;
                int e0 = nB + warpN * 64 + nt * 8 + 2 * tig;
                float2 fv;
                fv.x = acc[mt][nt][rp * 2]     + __ldg(&bias[e0]);
                fv.y = acc[mt][nt][rp * 2 + 1] + __ldg(&bias[e0 + 1]);
                *(float2*)&outF[(size_t)m * ETOT + e0] = fv;
            }
}

// ================= attention: S-in-registers, double-buffered K/V =================
#define QPITCH 136
#define VPITCH 72
#define KS_ELEM (64 * QPITCH)
#define VS_ELEM (128 * VPITCH)
#define ATTN_SMEM ((128 * QPITCH + 2 * KS_ELEM + 2 * VS_ELEM) * 2)

__device__ __forceinline__ void attn_load_kv(
    const __nv_bfloat16* kp, const __nv_bfloat16* vp,
    __nv_bfloat16* Ks, __nv_bfloat16* Vs, int kt, int tid)
{
#pragma unroll
    for (int t = 0; t < 4; t++) {
        int idx = tid + t * 256;
        int row = idx >> 4, s = idx & 15;
        cp16(smem_u32(&Ks[row * QPITCH + s * 8]), &kp[(size_t)(kt + row) * 128 + s * 8]);
        if (s < 8)
            cp16(smem_u32(&Vs[row * VPITCH + s * 8]), &vp[(size_t)(kt + row) * 128 + s * 8]);
        else
            cp16(smem_u32(&Vs[(64 + row) * VPITCH + (s - 8) * 8]),
                 &vp[(size_t)(kt + row) * 128 + s * 8]);
    }
}

__global__ __launch_bounds__(256, 2) void attn_mma3(
    const __nv_bfloat16* __restrict__ q2, const __nv_bfloat16* __restrict__ k2,
    const __nv_bfloat16* __restrict__ v2, float* __restrict__ attn)
{
    extern __shared__ __nv_bfloat16 smb[];
    __nv_bfloat16* Qs  = smb;                       // [128][136]
    __nv_bfloat16* Ks0 = Qs + 128 * QPITCH;         // [2][64][136]
    __nv_bfloat16* Vs0 = Ks0 + 2 * KS_ELEM;         // [2][128][72]

    const int tid = threadIdx.x;
    const int lane = tid & 31, warp = tid >> 5;     // warp 0..7 = m16 strip
    const int g = lane >> 2, tig = lane & 3;
    const int sel = lane >> 3, l8 = lane & 7;
    const int bh = blockIdx.y;
    const int qBase = blockIdx.x * 128;
    const __nv_bfloat16* qp = q2 + (size_t)bh * SEQ * 128;
    const __nv_bfloat16* kp = k2 + (size_t)bh * SEQ * 128;
    const __nv_bfloat16* vp = v2 + (size_t)bh * SEQ * 128;

    // Q (persistent)
#pragma unroll
    for (int t = 0; t < 8; t++) {
        int idx = tid + t * 256;
        int row = idx >> 4, s = idx & 15;
        cp16(smem_u32(&Qs[row * QPITCH + s * 8]), &qp[(size_t)(qBase + row) * 128 + s * 8]);
    }
    cp_commit();
    attn_load_kv(kp, vp, Ks0, Vs0, 0, tid);
    cp_commit();

    float oacc[8][4];
#pragma unroll
    for (int nt = 0; nt < 8; nt++)
#pragma unroll
        for (int r = 0; r < 4; r++) oacc[nt][r] = 0.f;

    for (int tile = 0; tile < 32; tile++) {
        const int buf = tile & 1;
        cp_wait0();
        __syncthreads();
        if (tile + 1 < 32) {
            attn_load_kv(kp, vp, Ks0 + (buf ^ 1) * KS_ELEM, Vs0 + (buf ^ 1) * VS_ELEM,
                         (tile + 1) * 64, tid);
            cp_commit();
        }
        const __nv_bfloat16* Ks = Ks0 + buf * KS_ELEM;
        const __nv_bfloat16* Vs = Vs0 + buf * VS_ELEM;

        // ---- phase 2: S[m16][64] = Q K^T (3-term) ----
        float sacc[8][4];
#pragma unroll
        for (int nt = 0; nt < 8; nt++)
#pragma unroll
            for (int r = 0; r < 4; r++) sacc[nt][r] = 0.f;

#pragma unroll
        for (int ks = 0; ks < 4; ks++) {
            const int kk = ks * 16;
            unsigned qhi[4], qlo[4];
            int arow = warp * 16 + (lane & 15);
            int ako = kk + ((lane >> 4) << 3);
            ldmat_x4(smem_u32(&Qs[arow * QPITCH + ako]), qhi);
            ldmat_x4(smem_u32(&Qs[arow * QPITCH + 64 + ako]), qlo);
#pragma unroll
            for (int p = 0; p < 4; p++) {
                unsigned kh_[4], kl_[4];
                int jrow = p * 16 + ((lane >> 4) << 3) + (lane & 7);
                int kc = kk + (((lane >> 3) & 1) << 3);
                ldmat_x4(smem_u32(&Ks[jrow * QPITCH + kc]), kh_);
                ldmat_x4(smem_u32(&Ks[jrow * QPITCH + 64 + kc]), kl_);
                mma_bf16(sacc[2 * p],     qhi, &kh_[0]);
                mma_bf16(sacc[2 * p + 1], qhi, &kh_[2]);
                mma_bf16(sacc[2 * p],     qlo, &kh_[0]);
                mma_bf16(sacc[2 * p + 1], qlo, &kh_[2]);
                mma_bf16(sacc[2 * p],     qhi, &kl_[0]);
                mma_bf16(sacc[2 * p + 1], qhi, &kl_[2]);
            }
        }

        // ---- phase 3: O += S V, S converted in registers per k16-chunk ----
#pragma unroll
        for (int t = 0; t < 4; t++) {
            unsigned ah[4], al[4];
#pragma unroll
            for (int j = 0; j < 2; j++) {
                float* s = sacc[2 * t + j];
                float s0 = s[0] * 0.125f, s1 = s[1] * 0.125f;
                float s2 = s[2] * 0.125f, s3 = s[3] * 0.125f;
                s0 = s0 > 0.f ? s0 : 0.f;  s1 = s1 > 0.f ? s1 : 0.f;
                s2 = s2 > 0.f ? s2 : 0.f;  s3 = s3 > 0.f ? s3 : 0.f;
                __nv_bfloat16 h0, h1, h2, h3, l0, l1, l2, l3;
                split_bf16(s0, h0, l0); split_bf16(s1, h1, l1);
                split_bf16(s2, h2, l2); split_bf16(s3, h3, l3);
                ah[2 * j]     = pack2(h0, h1);
                ah[2 * j + 1] = pack2(h2, h3);
                al[2 * j]     = pack2(l0, l1);
                al[2 * j + 1] = pack2(l2, l3);
            }
#pragma unroll
            for (int p = 0; p < 4; p++) {
                unsigned vh_[4], vl_[4];
                int krh = t * 16 + ((sel & 1) << 3) + l8;
                int nc = p * 16 + ((sel >> 1) << 3);
                ldmat_x4_t(smem_u32(&Vs[krh * VPITCH + nc]), vh_);
                ldmat_x4_t(smem_u32(&Vs[(64 + krh) * VPITCH + nc]), vl_);
                mma_bf16(oacc[2 * p],     ah, &vh_[0]);
                mma_bf16(oacc[2 * p + 1], ah, &vh_[2]);
                mma_bf16(oacc[2 * p],     al, &vh_[0]);
                mma_bf16(oacc[2 * p + 1], al, &vh_[2]);
                mma_bf16(oacc[2 * p],     ah, &vl_[0]);
                mma_bf16(oacc[2 * p + 1], ah, &vl_[2]);
            }
        }
    }

    const int b = bh >> 4, h = bh & 15;
#pragma unroll
    for (int nt = 0; nt < 8; nt++)
#pragma unroll
        for (int rp = 0; rp < 2; rp++) {
            int row = qBase + warp * 16 + g + rp * 8;
            int d0 = nt * 8 + 2 * tig;
            float2 fv;
            fv.x = oacc[nt][rp * 2];
            fv.y = oacc[nt][rp * 2 + 1];
            *(float2*)&attn[((size_t)b * SEQ + row) * ETOT + h * HDIM + d0] = fv;
        }
}

// ---------------- layernorm + gate; writes split bf16 gate ----------------
__global__ __launch_bounds__(256) void ln_gate(
    const float* __restrict__ a, const float* __restrict__ u,
    const float* __restrict__ gamma, const float* __restrict__ beta,
    __nv_bfloat16* __restrict__ o2)
{
    const int row = blockIdx.x;
    const int tid = threadIdx.x;
    const float* ar = a + (size_t)row * ETOT;
    float4 xv = *(const float4*)&ar[tid * 4];

    float s1 = xv.x + xv.y + xv.z + xv.w;
    float s2 = xv.x * xv.x + xv.y * xv.y + xv.z * xv.z + xv.w * xv.w;
#pragma unroll
    for (int o = 16; o > 0; o >>= 1) {
        s1 += __shfl_xor_sync(0xffffffffu, s1, o);
        s2 += __shfl_xor_sync(0xffffffffu, s2, o);
    }
    __shared__ float r1[8], r2[8];
    __shared__ float mu_s, inv_s;
    if ((tid & 31) == 0) { r1[tid >> 5] = s1; r2[tid >> 5] = s2; }
    __syncthreads();
    if (tid == 0) {
        float t1 = 0.f, t2 = 0.f;
#pragma unroll
        for (int i = 0; i < 8; i++) { t1 += r1[i]; t2 += r2[i]; }
        float mu = t1 * (1.f / ETOT);
        float var = t2 * (1.f / ETOT) - mu * mu;
        mu_s = mu;
        inv_s = rsqrtf(var + 1e-5f);
    }
    __syncthreads();
    const float mu = mu_s, inv = inv_s;

    float4 gv = *(const float4*)&gamma[tid * 4];
    float4 bv = *(const float4*)&beta[tid * 4];
    float4 uv = *(const float4*)&u[(size_t)row * ETOT + tid * 4];
    float o0 = ((xv.x - mu) * inv * gv.x + bv.x) * uv.x;
    float o1 = ((xv.y - mu) * inv * gv.y + bv.y) * uv.y;
    float o2v = ((xv.z - mu) * inv * gv.z + bv.z) * uv.z;
    float o3 = ((xv.w - mu) * inv * gv.w + bv.w) * uv.w;
    __nv_bfloat16 h0, h1, h2, h3, l0, l1, l2, l3;
    split_bf16(o0, h0, l0); split_bf16(o1, h1, l1);
    split_bf16(o2v, h2, l2); split_bf16(o3, h3, l3);
    uint2 hv; hv.x = pack2(h0, h1); hv.y = pack2(h2, h3);
    uint2 lv; lv.x = pack2(l0, l1); lv.y = pack2(l2, l3);
    *(uint2*)&o2[(size_t)row * 2048 + tid * 4]        = hv;
    *(uint2*)&o2[(size_t)row * 2048 + 1024 + tid * 4] = lv;
}

// ---------------- launch ----------------
extern "C" void kernel_launch(void* const* d_in, const int* in_sizes, int n_in,
                              void* d_out, int out_size)
{
    const float* x    = (const float*)d_in[0];
    const float* Wq   = (const float*)d_in[1];
    const float* bq   = (const float*)d_in[2];
    const float* Wk   = (const float*)d_in[3];
    const float* bk   = (const float*)d_in[4];
    const float* Wv   = (const float*)d_in[5];
    const float* bv   = (const float*)d_in[6];
    const float* Wu   = (const float*)d_in[7];
    const float* bu   = (const float*)d_in[8];
    const float* Wo   = (const float*)d_in[9];
    const float* bo   = (const float*)d_in[10];
    const float* ln_g = (const float*)d_in[11];
    const float* ln_b = (const float*)d_in[12];

    __nv_bfloat16 *x2, *w5, *g2, *q2, *k2, *v2;
    float *up, *ap;
    cudaGetSymbolAddress((void**)&x2, g_x2);
    cudaGetSymbolAddress((void**)&w5, g_w5);
    cudaGetSymbolAddress((void**)&g2, g_g2);
    cudaGetSymbolAddress((void**)&q2, g_q2);
    cudaGetSymbolAddress((void**)&k2, g_k2);
    cudaGetSymbolAddress((void**)&v2, g_v2);
    cudaGetSymbolAddress((void**)&up, g_u);
    cudaGetSymbolAddress((void**)&ap, g_attn);

    cudaFuncSetAttribute(proj_fused,
                         cudaFuncAttributeMaxDynamicSharedMemorySize, PROJ_SMEM);
    cudaFuncSetAttribute(proj_out,
                         cudaFuncAttributeMaxDynamicSharedMemorySize, PROJ_SMEM);
    cudaFuncSetAttribute(attn_mma3,
                         cudaFuncAttributeMaxDynamicSharedMemorySize, ATTN_SMEM);

    split_all_kernel<<<9216, 256>>>(x, Wq, Wk, Wv, Wu, Wo, x2, w5);

    proj_fused<<<dim3(32, 32), 256, PROJ_SMEM>>>(
        x2, w5, bq, bk, bv, bu, q2, k2, v2, up);

    attn_mma3<<<dim3(SEQ / 128, 32), 256, ATTN_SMEM>>>(q2, k2, v2, ap);

    ln_gate<<<MTOT, 256>>>(ap, up, ln_g, ln_b, g2);

    proj_out<<<dim3(8, 32), 256, PROJ_SMEM>>>(
        g2, w5 + (size_t)4096 * 2048, bo, (float*)d_out);
}